// round 10
// baseline (speedup 1.0000x reference)
#include <cuda_runtime.h>
#include <cuda_fp16.h>
#include <cstdint>
#include <math.h>

// Problem constants
#define T_TOKENS 1024
#define HID      2048
#define INTER    1024
#define NR       32
#define ETOT     40
#define TOPK     4
#define MAXP     (T_TOKENS * TOPK)
#define RSF      1.0f

#define NCH1     (HID / 64)     // 32 K64-iterations in stage 1
#define NCH2     (INTER / 64)   // 16 K64-iterations in stage 2
#define SMEM_SZ  66560

// ---------------- device scratch ------------------------------------------
__device__ int   g_topk_id[T_TOKENS][TOPK];
__device__ float g_topk_w [T_TOKENS][TOPK];
__device__ float g_zero_sum[T_TOKENS];
__device__ int   g_counts [NR];
__device__ int   g_offsets[NR + 1];
__device__ int   g_pair_tok[MAXP];
__device__ float g_pair_w [MAXP];
__device__ int   g_tok_pair[T_TOKENS][TOPK];
__device__ __align__(16) __half g_xch[(size_t)T_TOKENS * HID];  // rn(x) fp16, 4MB
__device__ __align__(16) __half g_h  [(size_t)MAXP * INTER];    // rn(h) fp16, 8MB
__device__ __align__(16) __half g_ye [(size_t)MAXP * HID];      // weighted ye fp16

// ---------------- helpers --------------------------------------------------
__device__ __forceinline__ uint32_t smem_u32(const void* p) {
    uint32_t a;
    asm("{ .reg .u64 t; cvta.to.shared.u64 t, %1; cvt.u32.u64 %0, t; }"
        : "=r"(a) : "l"(p));
    return a;
}
__device__ __forceinline__ uint32_t h2u(__half2 h) {
    return *reinterpret_cast<uint32_t*>(&h);
}

__device__ __forceinline__ void mma_f16(float* d, const uint32_t* a, const uint32_t* b) {
    asm volatile(
        "mma.sync.aligned.m16n8k16.row.col.f32.f16.f16.f32 "
        "{%0,%1,%2,%3}, {%4,%5,%6,%7}, {%8,%9}, {%0,%1,%2,%3};"
        : "+f"(d[0]), "+f"(d[1]), "+f"(d[2]), "+f"(d[3])
        : "r"(a[0]), "r"(a[1]), "r"(a[2]), "r"(a[3]), "r"(b[0]), "r"(b[1]));
}
#define LDSM4(R, addr) \
    asm volatile("ldmatrix.sync.aligned.m8n8.x4.shared.b16 {%0,%1,%2,%3}, [%4];" \
        : "=r"((R)[0]), "=r"((R)[1]), "=r"((R)[2]), "=r"((R)[3]) : "r"(addr))
#define LDSM2(R, addr) \
    asm volatile("ldmatrix.sync.aligned.m8n8.x2.shared.b16 {%0,%1}, [%2];" \
        : "=r"((R)[0]), "=r"((R)[1]) : "r"(addr))

// ---------------- kernel 0: convert x to fp16 + zero state ----------------
__global__ void conv_x_kernel(const float* __restrict__ x) {
    int gi = blockIdx.x * 256 + threadIdx.x;
    int i = gi * 4;
    float4 v = *(const float4*)(x + i);
    __half2 p0 = __floats2half2_rn(v.x, v.y);
    __half2 p1 = __floats2half2_rn(v.z, v.w);
    uint2 o; o.x = h2u(p0); o.y = h2u(p1);
    *(uint2*)(g_xch + i) = o;
    if (gi < MAXP) ((int*)g_tok_pair)[gi] = -1;
    if (gi >= MAXP && gi < MAXP + NR) g_counts[gi - MAXP] = 0;
}

// ---------------- kernel 1: router (fp32), 8 tokens per block -------------
__global__ void __launch_bounds__(128) router_kernel(
    const float* __restrict__ x, const float* __restrict__ rw,
    const float* __restrict__ bias)
{
    int t0 = blockIdx.x * 8;
    __shared__ float s_logit[8][ETOT];
    int tid = threadIdx.x;
    int warp = tid >> 5, lane = tid & 31;
    const float* xr = x + (size_t)t0 * HID;
    for (int e = warp; e < ETOT; e += 4) {
        const float* wr = rw + (size_t)e * HID;
        float a[8];
        #pragma unroll
        for (int u = 0; u < 8; u++) a[u] = 0.f;
        #pragma unroll 2
        for (int j = lane; j < HID; j += 32) {
            float wv = wr[j];
            #pragma unroll
            for (int u = 0; u < 8; u++) a[u] += xr[j + u * HID] * wv;
        }
        #pragma unroll
        for (int o = 16; o; o >>= 1)
            #pragma unroll
            for (int u = 0; u < 8; u++) a[u] += __shfl_xor_sync(0xffffffffu, a[u], o);
        if (lane == 0) {
            #pragma unroll
            for (int u = 0; u < 8; u++) s_logit[u][e] = a[u];
        }
    }
    __syncthreads();
    if (tid < 8) {
        int t = t0 + tid;
        float score[ETOT], sel[ETOT];
        for (int e = 0; e < ETOT; e++) {
            float s = 1.f / (1.f + expf(-s_logit[tid][e]));
            score[e] = s;
            sel[e] = s + bias[e];
        }
        float zsum = 0.f;
        for (int k = 0; k < TOPK; k++) {
            int best = -1; float bv = -1e30f;
            for (int e = 0; e < ETOT; e++)
                if (sel[e] > bv) { bv = sel[e]; best = e; }
            sel[best] = -1e30f;
            if (best < NR) {
                g_topk_id[t][k] = best;
                g_topk_w[t][k]  = score[best];
                atomicAdd(&g_counts[best], 1);
            } else {
                g_topk_id[t][k] = -1;
                g_topk_w[t][k]  = 0.f;
                zsum += score[best];
            }
        }
        g_zero_sum[t] = zsum;
    }
}

// ---------------- kernel 2: compaction (with fused offsets scan) ----------
__global__ void __launch_bounds__(1024) scatter_kernel() {
    int e = blockIdx.x;
    int t = threadIdx.x;
    __shared__ int s_cnt[NR];
    if (t < NR) s_cnt[t] = g_counts[t];

    float w = 0.f; int flag = 0; int kmatch = 0;
    #pragma unroll
    for (int k = 0; k < TOPK; k++)
        if (g_topk_id[t][k] == e) { flag = 1; w = g_topk_w[t][k]; kmatch = k; }

    __shared__ int warp_sums[32];
    int lane = t & 31, wid = t >> 5;
    int v = flag;
    #pragma unroll
    for (int o = 1; o < 32; o <<= 1) {
        int n = __shfl_up_sync(0xffffffffu, v, o);
        if (lane >= o) v += n;
    }
    if (lane == 31) warp_sums[wid] = v;
    __syncthreads();
    if (wid == 0) {
        int s = warp_sums[lane];
        #pragma unroll
        for (int o = 1; o < 32; o <<= 1) {
            int n = __shfl_up_sync(0xffffffffu, s, o);
            if (lane >= o) s += n;
        }
        warp_sums[lane] = s;
    }
    __syncthreads();
    int off = 0;
    for (int i = 0; i < e; i++) off += s_cnt[i];
    if (t == 0) {
        g_offsets[e] = off;
        if (e == NR - 1) g_offsets[NR] = off + s_cnt[e];
    }
    int incl = v + (wid > 0 ? warp_sums[wid - 1] : 0);
    if (flag) {
        int idx = off + incl - 1;
        g_pair_tok[idx] = t;
        g_pair_w[idx]   = w;
        g_tok_pair[t][kmatch] = idx;
    }
}

// ============ SMEM layout: 64B-row K32 sub-tiles, 2 subs per buffer ========
// swizzle: 16B-column index ^= (row>>1)&3

// ---------------- kernel 3: stage 1 (x@w1g, x@w1u, SwiGLU) -----------------
// CTA tile: 128 gathered tokens x 64 inter cols; warps 4(m) x 2(n).
// Outer iteration covers K=64 as two K32 sub-tiles; one sync per iteration.
__global__ void __launch_bounds__(256) stage1_kernel(
    const float* __restrict__ w1g, const float* __restrict__ w1u)
{
    int e   = blockIdx.y;
    int off = g_offsets[e];
    int cnt = g_offsets[e + 1] - off;
    int m0  = blockIdx.z * 128;
    if (m0 >= cnt) return;
    int i0 = blockIdx.x * 64;

    extern __shared__ __align__(16) char smem[];
    int* s_tok = (int*)smem;
    char* Abuf = smem + 1024;            // 2 bufs x 2 subs x 8192
    char* Gbuf = smem + 1024 + 32768;    // 2 bufs x 2 subs x 4096
    char* Ubuf = smem + 1024 + 49152;    // 2 bufs x 2 subs x 4096
    uint32_t sbase = smem_u32(smem);
    uint32_t aA = sbase + 1024, aG = aA + 32768, aU = aG + 16384;

    int tid = threadIdx.x, lane = tid & 31, wid = tid >> 5;
    int wm = wid >> 1, wn = wid & 1;
    if (tid < 128) {
        int m = m0 + tid;
        s_tok[tid] = (m < cnt) ? g_pair_tok[off + m] : -1;
    }
    __syncthreads();

    int lrow = lane & 7;
    int asel = lane >> 3;
    int arow = ((asel & 1) << 3) | lrow;
    int ahi  = asel >> 1;
    int aswz = (arow >> 1) & 3;
    int bhi  = (lane >> 3) & 1;
    int bswz = (lrow >> 1) & 3;

    const float* gbase = w1g + ((size_t)e * INTER + i0) * HID;
    const float* ubase = w1u + ((size_t)e * INTER + i0) * HID;

    float accG[2][4][4], accU[2][4][4];
    #pragma unroll
    for (int a = 0; a < 2; a++)
        #pragma unroll
        for (int b = 0; b < 4; b++)
            #pragma unroll
            for (int c = 0; c < 4; c++) { accG[a][b][c] = 0.f; accU[a][b][c] = 0.f; }

    uint4 rxa[2]; float4 rg[2], ru[2];
    // gs = global K32 sub-chunk index (k0 = gs*32)
    auto ldg_sub = [&](int gs) {
        int k0 = gs * 32;
        #pragma unroll
        for (int i = 0; i < 2; i++) {
            int idx = tid + i * 256; int r = idx >> 2, q = idx & 3;
            int tok = s_tok[r];
            rxa[i] = (tok >= 0) ? *(const uint4*)(g_xch + (size_t)tok * HID + k0 + q * 8)
                                : make_uint4(0u, 0u, 0u, 0u);
        }
        #pragma unroll
        for (int i = 0; i < 2; i++) {
            int idx = tid + i * 256; int r = idx >> 3, q = idx & 7;
            size_t go = (size_t)r * HID + k0 + q * 4;
            rg[i] = *(const float4*)(gbase + go);
            ru[i] = *(const float4*)(ubase + go);
        }
    };
    auto sts_sub = [&](int buf, int sub) {
        char* A = Abuf + buf * 16384 + sub * 8192;
        char* G = Gbuf + buf * 8192 + sub * 4096;
        char* U = Ubuf + buf * 8192 + sub * 4096;
        #pragma unroll
        for (int i = 0; i < 2; i++) {
            int idx = tid + i * 256; int r = idx >> 2, q = idx & 3;
            *(uint4*)(A + r * 64 + ((q ^ ((r >> 1) & 3)) << 4)) = rxa[i];
        }
        #pragma unroll
        for (int i = 0; i < 2; i++) {
            int idx = tid + i * 256; int r = idx >> 3, q = idx & 7;
            int so = r * 64 + ((((q >> 1) ^ ((r >> 1) & 3)) << 4) | ((q & 1) << 3));
            uint2 vg; vg.x = h2u(__floats2half2_rn(rg[i].x, rg[i].y));
                      vg.y = h2u(__floats2half2_rn(rg[i].z, rg[i].w));
            *(uint2*)(G + so) = vg;
            uint2 vu; vu.x = h2u(__floats2half2_rn(ru[i].x, ru[i].y));
                      vu.y = h2u(__floats2half2_rn(ru[i].z, ru[i].w));
            *(uint2*)(U + so) = vu;
        }
    };
    auto compute = [&](int buf, int sub) {
        uint32_t bA = aA + buf * 16384 + sub * 8192;
        uint32_t bG = aG + buf * 8192 + sub * 4096;
        uint32_t bU = aU + buf * 8192 + sub * 4096;
        #pragma unroll
        for (int s = 0; s < 2; s++) {
            uint32_t af[2][4];
            int ac = (((2 * s + ahi) ^ aswz) << 4) + arow * 64;
            LDSM4(af[0], bA + (wm * 2)     * 1024 + ac);
            LDSM4(af[1], bA + (wm * 2 + 1) * 1024 + ac);
            int bc = (((2 * s + bhi) ^ bswz) << 4) + lrow * 64;
            #pragma unroll
            for (int t = 0; t < 4; t++) {
                int nt = wn * 4 + t;
                uint32_t bg[2], bu[2];
                LDSM2(bg, bG + nt * 512 + bc);
                LDSM2(bu, bU + nt * 512 + bc);
                mma_f16(accG[0][t], af[0], bg);
                mma_f16(accG[1][t], af[1], bg);
                mma_f16(accU[0][t], af[0], bu);
                mma_f16(accU[1][t], af[1], bu);
            }
        }
    };

    ldg_sub(0); sts_sub(0, 0);
    ldg_sub(1); sts_sub(0, 1);
    __syncthreads();
    for (int it = 0; it < NCH1; ++it) {
        int cur = it & 1, nxt = cur ^ 1;
        bool pf = (it + 1) < NCH1;
        if (pf) ldg_sub((it + 1) * 2);
        compute(cur, 0);
        if (pf) { sts_sub(nxt, 0); ldg_sub((it + 1) * 2 + 1); }
        compute(cur, 1);
        if (pf) sts_sub(nxt, 1);
        __syncthreads();
    }

    // epilogue: h = silu(g)*u -> fp16 g_h
    #pragma unroll
    for (int mi = 0; mi < 2; mi++) {
        int rbase = wm * 32 + mi * 16 + (lane >> 2);
        #pragma unroll
        for (int t = 0; t < 4; t++) {
            int col = i0 + wn * 32 + t * 8 + (lane & 3) * 2;
            #pragma unroll
            for (int half = 0; half < 2; half++) {
                int rloc = rbase + half * 8;
                int m = m0 + rloc;
                if (m < cnt) {
                    float g0 = accG[mi][t][half * 2],     u0 = accU[mi][t][half * 2];
                    float g1 = accG[mi][t][half * 2 + 1], u1 = accU[mi][t][half * 2 + 1];
                    float h0 = (g0 / (1.f + __expf(-g0))) * u0;
                    float h1 = (g1 / (1.f + __expf(-g1))) * u1;
                    *(__half2*)(g_h + (size_t)(off + m) * INTER + col) =
                        __floats2half2_rn(h0, h1);
                }
            }
        }
    }
}

// ---------------- kernel 4: stage 2 (h @ w2, weighted) ---------------------
// CTA tile: 128 pairs x 128 hidden cols; warps 4(m) x 2(n).
__global__ void __launch_bounds__(256) stage2_kernel(const float* __restrict__ w2)
{
    int e   = blockIdx.y;
    int off = g_offsets[e];
    int cnt = g_offsets[e + 1] - off;
    int m0  = blockIdx.z * 128;
    if (m0 >= cnt) return;
    int n0 = blockIdx.x * 128;

    extern __shared__ __align__(16) char smem[];
    float* s_w = (float*)smem;
    char* Abuf = smem + 1024;            // 2 bufs x 2 subs x 8192
    char* Bbuf = smem + 1024 + 32768;    // 2 bufs x 2 subs x 8192
    uint32_t sbase = smem_u32(smem);
    uint32_t aA = sbase + 1024, aB = aA + 32768;

    int tid = threadIdx.x, lane = tid & 31, wid = tid >> 5;
    int wm = wid >> 1, wn = wid & 1;
    if (tid < 128) {
        int m = m0 + tid;
        s_w[tid] = (m < cnt) ? g_pair_w[off + m] : 0.f;
    }
    __syncthreads();

    int lrow = lane & 7;
    int asel = lane >> 3;
    int arow = ((asel & 1) << 3) | lrow;
    int ahi  = asel >> 1;
    int aswz = (arow >> 1) & 3;
    int bhi  = (lane >> 3) & 1;
    int bswz = (lrow >> 1) & 3;

    const float* bbase = w2 + ((size_t)e * HID + n0) * INTER;

    float acc[2][8][4];
    #pragma unroll
    for (int a = 0; a < 2; a++)
        #pragma unroll
        for (int b = 0; b < 8; b++)
            #pragma unroll
            for (int c = 0; c < 4; c++) acc[a][b][c] = 0.f;

    uint4 rxa[2]; float4 rb[4];
    auto ldg_sub = [&](int gs) {
        int k0 = gs * 32;
        #pragma unroll
        for (int i = 0; i < 2; i++) {
            int idx = tid + i * 256; int r = idx >> 2, q = idx & 3;
            int m = m0 + r;
            rxa[i] = (m < cnt) ? *(const uint4*)(g_h + (size_t)(off + m) * INTER + k0 + q * 8)
                               : make_uint4(0u, 0u, 0u, 0u);
        }
        #pragma unroll
        for (int i = 0; i < 4; i++) {
            int idx = tid + i * 256; int r = idx >> 3, q = idx & 7;
            rb[i] = *(const float4*)(bbase + (size_t)r * INTER + k0 + q * 4);
        }
    };
    auto sts_sub = [&](int buf, int sub) {
        char* A = Abuf + buf * 16384 + sub * 8192;
        char* B = Bbuf + buf * 16384 + sub * 8192;
        #pragma unroll
        for (int i = 0; i < 2; i++) {
            int idx = tid + i * 256; int r = idx >> 2, q = idx & 3;
            *(uint4*)(A + r * 64 + ((q ^ ((r >> 1) & 3)) << 4)) = rxa[i];
        }
        #pragma unroll
        for (int i = 0; i < 4; i++) {
            int idx = tid + i * 256; int r = idx >> 3, q = idx & 7;
            int so = r * 64 + ((((q >> 1) ^ ((r >> 1) & 3)) << 4) | ((q & 1) << 3));
            uint2 vb; vb.x = h2u(__floats2half2_rn(rb[i].x, rb[i].y));
                      vb.y = h2u(__floats2half2_rn(rb[i].z, rb[i].w));
            *(uint2*)(B + so) = vb;
        }
    };
    auto compute = [&](int buf, int sub) {
        uint32_t bA = aA + buf * 16384 + sub * 8192;
        uint32_t bB = aB + buf * 16384 + sub * 8192;
        #pragma unroll
        for (int s = 0; s < 2; s++) {
            uint32_t af[2][4];
            int ac = (((2 * s + ahi) ^ aswz) << 4) + arow * 64;
            LDSM4(af[0], bA + (wm * 2)     * 1024 + ac);
            LDSM4(af[1], bA + (wm * 2 + 1) * 1024 + ac);
            int bc = (((2 * s + bhi) ^ bswz) << 4) + lrow * 64;
            #pragma unroll
            for (int t = 0; t < 8; t++) {
                int nt = wn * 8 + t;
                uint32_t bf[2];
                LDSM2(bf, bB + nt * 512 + bc);
                mma_f16(acc[0][t], af[0], bf);
                mma_f16(acc[1][t], af[1], bf);
            }
        }
    };

    ldg_sub(0); sts_sub(0, 0);
    ldg_sub(1); sts_sub(0, 1);
    __syncthreads();
    for (int it = 0; it < NCH2; ++it) {
        int cur = it & 1, nxt = cur ^ 1;
        bool pf = (it + 1) < NCH2;
        if (pf) ldg_sub((it + 1) * 2);
        compute(cur, 0);
        if (pf) { sts_sub(nxt, 0); ldg_sub((it + 1) * 2 + 1); }
        compute(cur, 1);
        if (pf) sts_sub(nxt, 1);
        __syncthreads();
    }

    // epilogue: weighted rows into g_ye (fp16)
    #pragma unroll
    for (int mi = 0; mi < 2; mi++) {
        int rbase = wm * 32 + mi * 16 + (lane >> 2);
        #pragma unroll
        for (int t = 0; t < 8; t++) {
            int col = n0 + wn * 64 + t * 8 + (lane & 3) * 2;
            #pragma unroll
            for (int half = 0; half < 2; half++) {
                int rloc = rbase + half * 8;
                int m = m0 + rloc;
                if (m < cnt) {
                    float pw = s_w[rloc];
                    *(__half2*)(g_ye + (size_t)(off + m) * HID + col) =
                        __floats2half2_rn(pw * acc[mi][t][half * 2],
                                          pw * acc[mi][t][half * 2 + 1]);
                }
            }
        }
    }
}

// ---------------- kernel 5: combine ---------------------------------------
__global__ void __launch_bounds__(256) combine_kernel(
    const float* __restrict__ x, float* __restrict__ out)
{
    int t = blockIdx.x;
    int c = threadIdx.x * 8;
    float zs = g_zero_sum[t];
    const float* xr = x + (size_t)t * HID + c;
    float4 a0 = *(const float4*)xr;
    float4 a1 = *(const float4*)(xr + 4);
    a0.x *= zs; a0.y *= zs; a0.z *= zs; a0.w *= zs;
    a1.x *= zs; a1.y *= zs; a1.z *= zs; a1.w *= zs;
    #pragma unroll
    for (int k = 0; k < TOPK; k++) {
        int p = g_tok_pair[t][k];
        if (p >= 0) {
            uint4 raw = *(const uint4*)(g_ye + (size_t)p * HID + c);
            __half2* hp = (__half2*)&raw;
            float2 f0 = __half22float2(hp[0]);
            float2 f1 = __half22float2(hp[1]);
            float2 f2 = __half22float2(hp[2]);
            float2 f3 = __half22float2(hp[3]);
            a0.x += f0.x; a0.y += f0.y; a0.z += f1.x; a0.w += f1.y;
            a1.x += f2.x; a1.y += f2.y; a1.z += f3.x; a1.w += f3.y;
        }
    }
    a0.x *= RSF; a0.y *= RSF; a0.z *= RSF; a0.w *= RSF;
    a1.x *= RSF; a1.y *= RSF; a1.z *= RSF; a1.w *= RSF;
    float* o = out + (size_t)t * HID + c;
    *(float4*)o = a0;
    *(float4*)(o + 4) = a1;
}

// ---------------- launch ---------------------------------------------------
extern "C" void kernel_launch(void* const* d_in, const int* in_sizes, int n_in,
                              void* d_out, int out_size)
{
    const float* x    = (const float*)d_in[0];
    const float* rw   = (const float*)d_in[1];
    const float* bias = (const float*)d_in[2];
    const float* w1g  = (const float*)d_in[3];
    const float* w1u  = (const float*)d_in[4];
    const float* w2   = (const float*)d_in[5];
    float* out = (float*)d_out;

    cudaFuncSetAttribute(stage1_kernel, cudaFuncAttributeMaxDynamicSharedMemorySize, SMEM_SZ);
    cudaFuncSetAttribute(stage2_kernel, cudaFuncAttributeMaxDynamicSharedMemorySize, SMEM_SZ);

    conv_x_kernel<<<(T_TOKENS * HID) / (256 * 4), 256>>>(x);
    router_kernel<<<T_TOKENS / 8, 128>>>(x, rw, bias);
    scatter_kernel<<<NR, 1024>>>();
    // grid.z = 2: max 256 tokens/expert (binomial 15-sigma bound; mean ~102)
    stage1_kernel<<<dim3(INTER / 64, NR, 2), 256, SMEM_SZ>>>(w1g, w1u);
    stage2_kernel<<<dim3(HID / 128, NR, 2), 256, SMEM_SZ>>>(w2);
    combine_kernel<<<T_TOKENS, 256>>>(x, out);
}

// round 11
// speedup vs baseline: 1.1252x; 1.1252x over previous
#include <cuda_runtime.h>
#include <cuda_fp16.h>
#include <cstdint>
#include <math.h>

// Problem constants
#define T_TOKENS 1024
#define HID      2048
#define INTER    1024
#define NR       32
#define ETOT     40
#define TOPK     4
#define MAXP     (T_TOKENS * TOPK)
#define RSF      1.0f

#define CH1      (HID / 32)     // 64 K-chunks (chunk K = 32) in stage 1
#define CH2      (INTER / 32)   // 32 K-chunks in stage 2
#define SMEM_SZ  33792

// ---------------- device scratch ------------------------------------------
__device__ int   g_topk_id[T_TOKENS][TOPK];
__device__ float g_topk_w [T_TOKENS][TOPK];
__device__ float g_zero_sum[T_TOKENS];
__device__ int   g_counts [NR];
__device__ int   g_offsets[NR + 1];
__device__ int   g_pair_tok[MAXP];
__device__ float g_pair_w [MAXP];
__device__ int   g_tok_pair[T_TOKENS][TOPK];
__device__ __align__(16) __half g_xch[(size_t)T_TOKENS * HID];  // rn(x) fp16, 4MB
__device__ __align__(16) __half g_h  [(size_t)MAXP * INTER];    // rn(h) fp16, 8MB
__device__ __align__(16) __half g_ye [(size_t)MAXP * HID];      // weighted ye fp16

// ---------------- helpers --------------------------------------------------
__device__ __forceinline__ uint32_t smem_u32(const void* p) {
    uint32_t a;
    asm("{ .reg .u64 t; cvta.to.shared.u64 t, %1; cvt.u32.u64 %0, t; }"
        : "=r"(a) : "l"(p));
    return a;
}
__device__ __forceinline__ uint32_t h2u(__half2 h) {
    return *reinterpret_cast<uint32_t*>(&h);
}

__device__ __forceinline__ void mma_f16(float* d, const uint32_t* a, const uint32_t* b) {
    asm volatile(
        "mma.sync.aligned.m16n8k16.row.col.f32.f16.f16.f32 "
        "{%0,%1,%2,%3}, {%4,%5,%6,%7}, {%8,%9}, {%0,%1,%2,%3};"
        : "+f"(d[0]), "+f"(d[1]), "+f"(d[2]), "+f"(d[3])
        : "r"(a[0]), "r"(a[1]), "r"(a[2]), "r"(a[3]), "r"(b[0]), "r"(b[1]));
}
#define LDSM4(R, addr) \
    asm volatile("ldmatrix.sync.aligned.m8n8.x4.shared.b16 {%0,%1,%2,%3}, [%4];" \
        : "=r"((R)[0]), "=r"((R)[1]), "=r"((R)[2]), "=r"((R)[3]) : "r"(addr))
#define LDSM2(R, addr) \
    asm volatile("ldmatrix.sync.aligned.m8n8.x2.shared.b16 {%0,%1}, [%2];" \
        : "=r"((R)[0]), "=r"((R)[1]) : "r"(addr))

// ---------------- kernel 0: convert x to fp16 + zero state ----------------
__global__ void conv_x_kernel(const float* __restrict__ x) {
    int gi = blockIdx.x * 256 + threadIdx.x;
    int i = gi * 4;
    float4 v = *(const float4*)(x + i);
    __half2 p0 = __floats2half2_rn(v.x, v.y);
    __half2 p1 = __floats2half2_rn(v.z, v.w);
    uint2 o; o.x = h2u(p0); o.y = h2u(p1);
    *(uint2*)(g_xch + i) = o;
    if (gi < MAXP) ((int*)g_tok_pair)[gi] = -1;
    if (gi >= MAXP && gi < MAXP + NR) g_counts[gi - MAXP] = 0;
}

// ---------------- kernel 1: router (fp32), 8 tokens per block -------------
__global__ void __launch_bounds__(128) router_kernel(
    const float* __restrict__ x, const float* __restrict__ rw,
    const float* __restrict__ bias)
{
    int t0 = blockIdx.x * 8;
    __shared__ float s_logit[8][ETOT];
    int tid = threadIdx.x;
    int warp = tid >> 5, lane = tid & 31;
    const float* xr = x + (size_t)t0 * HID;
    for (int e = warp; e < ETOT; e += 4) {
        const float* wr = rw + (size_t)e * HID;
        float a[8];
        #pragma unroll
        for (int u = 0; u < 8; u++) a[u] = 0.f;
        #pragma unroll 2
        for (int j = lane; j < HID; j += 32) {
            float wv = wr[j];
            #pragma unroll
            for (int u = 0; u < 8; u++) a[u] += xr[j + u * HID] * wv;
        }
        #pragma unroll
        for (int o = 16; o; o >>= 1)
            #pragma unroll
            for (int u = 0; u < 8; u++) a[u] += __shfl_xor_sync(0xffffffffu, a[u], o);
        if (lane == 0) {
            #pragma unroll
            for (int u = 0; u < 8; u++) s_logit[u][e] = a[u];
        }
    }
    __syncthreads();
    if (tid < 8) {
        int t = t0 + tid;
        float score[ETOT], sel[ETOT];
        for (int e = 0; e < ETOT; e++) {
            float s = 1.f / (1.f + expf(-s_logit[tid][e]));
            score[e] = s;
            sel[e] = s + bias[e];
        }
        float zsum = 0.f;
        for (int k = 0; k < TOPK; k++) {
            int best = -1; float bv = -1e30f;
            for (int e = 0; e < ETOT; e++)
                if (sel[e] > bv) { bv = sel[e]; best = e; }
            sel[best] = -1e30f;
            if (best < NR) {
                g_topk_id[t][k] = best;
                g_topk_w[t][k]  = score[best];
                atomicAdd(&g_counts[best], 1);
            } else {
                g_topk_id[t][k] = -1;
                g_topk_w[t][k]  = 0.f;
                zsum += score[best];
            }
        }
        g_zero_sum[t] = zsum;
    }
}

// ---------------- kernel 2: compaction (with fused offsets scan) ----------
__global__ void __launch_bounds__(1024) scatter_kernel() {
    int e = blockIdx.x;
    int t = threadIdx.x;
    __shared__ int s_cnt[NR];
    if (t < NR) s_cnt[t] = g_counts[t];

    float w = 0.f; int flag = 0; int kmatch = 0;
    #pragma unroll
    for (int k = 0; k < TOPK; k++)
        if (g_topk_id[t][k] == e) { flag = 1; w = g_topk_w[t][k]; kmatch = k; }

    __shared__ int warp_sums[32];
    int lane = t & 31, wid = t >> 5;
    int v = flag;
    #pragma unroll
    for (int o = 1; o < 32; o <<= 1) {
        int n = __shfl_up_sync(0xffffffffu, v, o);
        if (lane >= o) v += n;
    }
    if (lane == 31) warp_sums[wid] = v;
    __syncthreads();
    if (wid == 0) {
        int s = warp_sums[lane];
        #pragma unroll
        for (int o = 1; o < 32; o <<= 1) {
            int n = __shfl_up_sync(0xffffffffu, s, o);
            if (lane >= o) s += n;
        }
        warp_sums[lane] = s;
    }
    __syncthreads();
    int off = 0;
    for (int i = 0; i < e; i++) off += s_cnt[i];
    if (t == 0) {
        g_offsets[e] = off;
        if (e == NR - 1) g_offsets[NR] = off + s_cnt[e];
    }
    int incl = v + (wid > 0 ? warp_sums[wid - 1] : 0);
    if (flag) {
        int idx = off + incl - 1;
        g_pair_tok[idx] = t;
        g_pair_w[idx]   = w;
        g_tok_pair[t][kmatch] = idx;
    }
}

// ============ SMEM layout: natural row-major half tiles, 64B rows ==========
// swizzle: 16B-column index ^= (row>>1)&3

// ---------------- kernel 3: stage 1 (x@w1g, x@w1u, SwiGLU) -----------------
// CTA tile: 128 gathered tokens x 64 inter cols; warps 4(m) x 2(n).
__global__ void __launch_bounds__(256, 2) stage1_kernel(
    const float* __restrict__ w1g, const float* __restrict__ w1u)
{
    int e   = blockIdx.y;
    int off = g_offsets[e];
    int cnt = g_offsets[e + 1] - off;
    int m0  = blockIdx.z * 128;
    if (m0 >= cnt) return;
    int i0 = blockIdx.x * 64;

    extern __shared__ __align__(16) char smem[];
    int* s_tok = (int*)smem;
    char* Abuf = smem + 1024;            // 2 x 8192 (128 rows x 64B)
    char* Gbuf = smem + 1024 + 16384;    // 2 x 4096 (64 rows x 64B)
    char* Ubuf = smem + 1024 + 24576;    // 2 x 4096
    uint32_t sbase = smem_u32(smem);
    uint32_t aA = sbase + 1024, aG = aA + 16384, aU = aG + 8192;

    int tid = threadIdx.x, lane = tid & 31, wid = tid >> 5;
    int wm = wid >> 1, wn = wid & 1;
    if (tid < 128) {
        int m = m0 + tid;
        s_tok[tid] = (m < cnt) ? g_pair_tok[off + m] : -1;
    }
    __syncthreads();

    int lrow = lane & 7;
    int asel = lane >> 3;
    int arow = ((asel & 1) << 3) | lrow;
    int ahi  = asel >> 1;
    int aswz = (arow >> 1) & 3;
    int bhi  = (lane >> 3) & 1;
    int bswz = (lrow >> 1) & 3;

    const float* gbase = w1g + ((size_t)e * INTER + i0) * HID;
    const float* ubase = w1u + ((size_t)e * INTER + i0) * HID;

    float accG[2][4][4], accU[2][4][4];
    #pragma unroll
    for (int a = 0; a < 2; a++)
        #pragma unroll
        for (int b = 0; b < 4; b++)
            #pragma unroll
            for (int c = 0; c < 4; c++) { accG[a][b][c] = 0.f; accU[a][b][c] = 0.f; }

    uint4 rxa[2]; float4 rg[2], ru[2];
    auto ldg_chunk = [&](int it) {
        int k0 = it * 32;
        #pragma unroll
        for (int i = 0; i < 2; i++) {
            int idx = tid + i * 256; int r = idx >> 2, q = idx & 3;
            int tok = s_tok[r];
            rxa[i] = (tok >= 0) ? *(const uint4*)(g_xch + (size_t)tok * HID + k0 + q * 8)
                                : make_uint4(0u, 0u, 0u, 0u);
        }
        #pragma unroll
        for (int i = 0; i < 2; i++) {
            int idx = tid + i * 256; int r = idx >> 3, q = idx & 7;
            size_t go = (size_t)r * HID + k0 + q * 4;
            rg[i] = *(const float4*)(gbase + go);
            ru[i] = *(const float4*)(ubase + go);
        }
    };
    auto sts_chunk = [&](int buf) {
        char* A = Abuf + buf * 8192;
        char* G = Gbuf + buf * 4096;
        char* U = Ubuf + buf * 4096;
        #pragma unroll
        for (int i = 0; i < 2; i++) {
            int idx = tid + i * 256; int r = idx >> 2, q = idx & 3;
            *(uint4*)(A + r * 64 + ((q ^ ((r >> 1) & 3)) << 4)) = rxa[i];
        }
        #pragma unroll
        for (int i = 0; i < 2; i++) {
            int idx = tid + i * 256; int r = idx >> 3, q = idx & 7;
            int so = r * 64 + ((((q >> 1) ^ ((r >> 1) & 3)) << 4) | ((q & 1) << 3));
            uint2 vg; vg.x = h2u(__floats2half2_rn(rg[i].x, rg[i].y));
                      vg.y = h2u(__floats2half2_rn(rg[i].z, rg[i].w));
            *(uint2*)(G + so) = vg;
            uint2 vu; vu.x = h2u(__floats2half2_rn(ru[i].x, ru[i].y));
                      vu.y = h2u(__floats2half2_rn(ru[i].z, ru[i].w));
            *(uint2*)(U + so) = vu;
        }
    };
    auto compute = [&](int buf) {
        uint32_t bA = aA + buf * 8192;
        uint32_t bG = aG + buf * 4096;
        uint32_t bU = aU + buf * 4096;
        #pragma unroll
        for (int s = 0; s < 2; s++) {
            uint32_t af[2][4];
            int ac = (((2 * s + ahi) ^ aswz) << 4) + arow * 64;
            LDSM4(af[0], bA + (wm * 2)     * 1024 + ac);
            LDSM4(af[1], bA + (wm * 2 + 1) * 1024 + ac);
            int bc = (((2 * s + bhi) ^ bswz) << 4) + lrow * 64;
            #pragma unroll
            for (int t = 0; t < 4; t++) {
                int nt = wn * 4 + t;
                uint32_t bg[2], bu[2];
                LDSM2(bg, bG + nt * 512 + bc);
                LDSM2(bu, bU + nt * 512 + bc);
                mma_f16(accG[0][t], af[0], bg);
                mma_f16(accG[1][t], af[1], bg);
                mma_f16(accU[0][t], af[0], bu);
                mma_f16(accU[1][t], af[1], bu);
            }
        }
    };

    ldg_chunk(0); sts_chunk(0);
    __syncthreads();
    for (int it = 0; it < CH1; ++it) {
        bool pf = (it + 1) < CH1;
        if (pf) ldg_chunk(it + 1);
        compute(it & 1);
        if (pf) sts_chunk((it + 1) & 1);
        __syncthreads();
    }

    // epilogue: h = silu(g)*u -> fp16 g_h
    #pragma unroll
    for (int mi = 0; mi < 2; mi++) {
        int rbase = wm * 32 + mi * 16 + (lane >> 2);
        #pragma unroll
        for (int t = 0; t < 4; t++) {
            int col = i0 + wn * 32 + t * 8 + (lane & 3) * 2;
            #pragma unroll
            for (int half = 0; half < 2; half++) {
                int rloc = rbase + half * 8;
                int m = m0 + rloc;
                if (m < cnt) {
                    float g0 = accG[mi][t][half * 2],     u0 = accU[mi][t][half * 2];
                    float g1 = accG[mi][t][half * 2 + 1], u1 = accU[mi][t][half * 2 + 1];
                    float h0 = (g0 / (1.f + __expf(-g0))) * u0;
                    float h1 = (g1 / (1.f + __expf(-g1))) * u1;
                    *(__half2*)(g_h + (size_t)(off + m) * INTER + col) =
                        __floats2half2_rn(h0, h1);
                }
            }
        }
    }
}

// ---------------- kernel 4: stage 2 (h @ w2, weighted) ---------------------
// CTA tile: 128 pairs x 128 hidden cols; warps 4(m) x 2(n).
__global__ void __launch_bounds__(256, 2) stage2_kernel(const float* __restrict__ w2)
{
    int e   = blockIdx.y;
    int off = g_offsets[e];
    int cnt = g_offsets[e + 1] - off;
    int m0  = blockIdx.z * 128;
    if (m0 >= cnt) return;
    int n0 = blockIdx.x * 128;

    extern __shared__ __align__(16) char smem[];
    float* s_w = (float*)smem;
    char* Abuf = smem + 1024;            // 2 x 8192
    char* Bbuf = smem + 1024 + 16384;    // 2 x 8192 (128 n-rows x 64B)
    uint32_t sbase = smem_u32(smem);
    uint32_t aA = sbase + 1024, aB = aA + 16384;

    int tid = threadIdx.x, lane = tid & 31, wid = tid >> 5;
    int wm = wid >> 1, wn = wid & 1;
    if (tid < 128) {
        int m = m0 + tid;
        s_w[tid] = (m < cnt) ? g_pair_w[off + m] : 0.f;
    }
    __syncthreads();

    int lrow = lane & 7;
    int asel = lane >> 3;
    int arow = ((asel & 1) << 3) | lrow;
    int ahi  = asel >> 1;
    int aswz = (arow >> 1) & 3;
    int bhi  = (lane >> 3) & 1;
    int bswz = (lrow >> 1) & 3;

    const float* bbase = w2 + ((size_t)e * HID + n0) * INTER;

    float acc[2][8][4];
    #pragma unroll
    for (int a = 0; a < 2; a++)
        #pragma unroll
        for (int b = 0; b < 8; b++)
            #pragma unroll
            for (int c = 0; c < 4; c++) acc[a][b][c] = 0.f;

    uint4 rxa[2]; float4 rb0[2], rb1[2];
    auto ldg_chunk = [&](int it) {
        int k0 = it * 32;
        #pragma unroll
        for (int i = 0; i < 2; i++) {
            int idx = tid + i * 256; int r = idx >> 2, q = idx & 3;
            int m = m0 + r;
            rxa[i] = (m < cnt) ? *(const uint4*)(g_h + (size_t)(off + m) * INTER + k0 + q * 8)
                               : make_uint4(0u, 0u, 0u, 0u);
            size_t o = (size_t)r * INTER + k0 + q * 8;
            rb0[i] = *(const float4*)(bbase + o);
            rb1[i] = *(const float4*)(bbase + o + 4);
        }
    };
    auto sts_chunk = [&](int buf) {
        #pragma unroll
        for (int i = 0; i < 2; i++) {
            int idx = tid + i * 256; int r = idx >> 2, q = idx & 3;
            int so = r * 64 + ((q ^ ((r >> 1) & 3)) << 4);
            *(uint4*)(Abuf + buf * 8192 + so) = rxa[i];
            uint4 vb;
            vb.x = h2u(__floats2half2_rn(rb0[i].x, rb0[i].y));
            vb.y = h2u(__floats2half2_rn(rb0[i].z, rb0[i].w));
            vb.z = h2u(__floats2half2_rn(rb1[i].x, rb1[i].y));
            vb.w = h2u(__floats2half2_rn(rb1[i].z, rb1[i].w));
            *(uint4*)(Bbuf + buf * 8192 + so) = vb;
        }
    };
    auto compute = [&](int buf) {
        uint32_t bA = aA + buf * 8192;
        uint32_t bB = aB + buf * 8192;
        #pragma unroll
        for (int s = 0; s < 2; s++) {
            uint32_t af[2][4];
            int ac = (((2 * s + ahi) ^ aswz) << 4) + arow * 64;
            LDSM4(af[0], bA + (wm * 2)     * 1024 + ac);
            LDSM4(af[1], bA + (wm * 2 + 1) * 1024 + ac);
            int bc = (((2 * s + bhi) ^ bswz) << 4) + lrow * 64;
            #pragma unroll
            for (int t = 0; t < 8; t++) {
                int nt = wn * 8 + t;
                uint32_t bf[2];
                LDSM2(bf, bB + nt * 512 + bc);
                mma_f16(acc[0][t], af[0], bf);
                mma_f16(acc[1][t], af[1], bf);
            }
        }
    };

    ldg_chunk(0); sts_chunk(0);
    __syncthreads();
    for (int it = 0; it < CH2; ++it) {
        bool pf = (it + 1) < CH2;
        if (pf) ldg_chunk(it + 1);
        compute(it & 1);
        if (pf) sts_chunk((it + 1) & 1);
        __syncthreads();
    }

    // epilogue: weighted rows into g_ye (fp16)
    #pragma unroll
    for (int mi = 0; mi < 2; mi++) {
        int rbase = wm * 32 + mi * 16 + (lane >> 2);
        #pragma unroll
        for (int t = 0; t < 8; t++) {
            int col = n0 + wn * 64 + t * 8 + (lane & 3) * 2;
            #pragma unroll
            for (int half = 0; half < 2; half++) {
                int rloc = rbase + half * 8;
                int m = m0 + rloc;
                if (m < cnt) {
                    float pw = s_w[rloc];
                    *(__half2*)(g_ye + (size_t)(off + m) * HID + col) =
                        __floats2half2_rn(pw * acc[mi][t][half * 2],
                                          pw * acc[mi][t][half * 2 + 1]);
                }
            }
        }
    }
}

// ---------------- kernel 5: combine ---------------------------------------
__global__ void __launch_bounds__(256) combine_kernel(
    const float* __restrict__ x, float* __restrict__ out)
{
    int t = blockIdx.x;
    int c = threadIdx.x * 8;
    float zs = g_zero_sum[t];
    const float* xr = x + (size_t)t * HID + c;
    float4 a0 = *(const float4*)xr;
    float4 a1 = *(const float4*)(xr + 4);
    a0.x *= zs; a0.y *= zs; a0.z *= zs; a0.w *= zs;
    a1.x *= zs; a1.y *= zs; a1.z *= zs; a1.w *= zs;
    #pragma unroll
    for (int k = 0; k < TOPK; k++) {
        int p = g_tok_pair[t][k];
        if (p >= 0) {
            uint4 raw = *(const uint4*)(g_ye + (size_t)p * HID + c);
            __half2* hp = (__half2*)&raw;
            float2 f0 = __half22float2(hp[0]);
            float2 f1 = __half22float2(hp[1]);
            float2 f2 = __half22float2(hp[2]);
            float2 f3 = __half22float2(hp[3]);
            a0.x += f0.x; a0.y += f0.y; a0.z += f1.x; a0.w += f1.y;
            a1.x += f2.x; a1.y += f2.y; a1.z += f3.x; a1.w += f3.y;
        }
    }
    a0.x *= RSF; a0.y *= RSF; a0.z *= RSF; a0.w *= RSF;
    a1.x *= RSF; a1.y *= RSF; a1.z *= RSF; a1.w *= RSF;
    float* o = out + (size_t)t * HID + c;
    *(float4*)o = a0;
    *(float4*)(o + 4) = a1;
}

// ---------------- launch ---------------------------------------------------
extern "C" void kernel_launch(void* const* d_in, const int* in_sizes, int n_in,
                              void* d_out, int out_size)
{
    const float* x    = (const float*)d_in[0];
    const float* rw   = (const float*)d_in[1];
    const float* bias = (const float*)d_in[2];
    const float* w1g  = (const float*)d_in[3];
    const float* w1u  = (const float*)d_in[4];
    const float* w2   = (const float*)d_in[5];
    float* out = (float*)d_out;

    cudaFuncSetAttribute(stage1_kernel, cudaFuncAttributeMaxDynamicSharedMemorySize, SMEM_SZ);
    cudaFuncSetAttribute(stage2_kernel, cudaFuncAttributeMaxDynamicSharedMemorySize, SMEM_SZ);

    conv_x_kernel<<<(T_TOKENS * HID) / (256 * 4), 256>>>(x);
    router_kernel<<<T_TOKENS / 8, 128>>>(x, rw, bias);
    scatter_kernel<<<NR, 1024>>>();
    stage1_kernel<<<dim3(INTER / 64, NR, 8), 256, SMEM_SZ>>>(w1g, w1u);
    stage2_kernel<<<dim3(HID / 128, NR, 8), 256, SMEM_SZ>>>(w2);
    combine_kernel<<<T_TOKENS, 256>>>(x, out);
}

// round 14
// speedup vs baseline: 1.5543x; 1.3814x over previous
#include <cuda_runtime.h>
#include <cuda_fp16.h>
#include <cstdint>
#include <math.h>

// Problem constants
#define T_TOKENS 1024
#define HID      2048
#define INTER    1024
#define NR       32
#define ETOT     40
#define TOPK     4
#define MAXP     (T_TOKENS * TOPK)
#define RSF      1.0f

#define CH1      (HID / 32)     // 64 K-chunks (chunk K = 32) in stage 1
#define CH2      (INTER / 32)   // 32 K-chunks in stage 2
#define SMEM_SZ  33792

// ---------------- device scratch ------------------------------------------
__device__ int   g_topk_id[T_TOKENS][TOPK];
__device__ float g_topk_w [T_TOKENS][TOPK];
__device__ float g_zero_sum[T_TOKENS];
__device__ int   g_counts [NR];
__device__ int   g_offsets[NR + 1];
__device__ int   g_pair_tok[MAXP];
__device__ float g_pair_w [MAXP];
__device__ int   g_tok_pair[T_TOKENS][TOPK];
__device__ __align__(16) __half g_xch[(size_t)T_TOKENS * HID];  // rn(x) fp16, 4MB
__device__ __align__(16) __half g_h  [(size_t)MAXP * INTER];    // rn(h) fp16, 8MB
__device__ __align__(16) __half g_ye [(size_t)MAXP * HID];      // weighted ye fp16

// ---------------- helpers --------------------------------------------------
__device__ __forceinline__ uint32_t smem_u32(const void* p) {
    uint32_t a;
    asm("{ .reg .u64 t; cvta.to.shared.u64 t, %1; cvt.u32.u64 %0, t; }"
        : "=r"(a) : "l"(p));
    return a;
}
__device__ __forceinline__ uint32_t h2u(__half2 h) {
    return *reinterpret_cast<uint32_t*>(&h);
}

__device__ __forceinline__ void mma_f16(float* d, const uint32_t* a, const uint32_t* b) {
    asm volatile(
        "mma.sync.aligned.m16n8k16.row.col.f32.f16.f16.f32 "
        "{%0,%1,%2,%3}, {%4,%5,%6,%7}, {%8,%9}, {%0,%1,%2,%3};"
        : "+f"(d[0]), "+f"(d[1]), "+f"(d[2]), "+f"(d[3])
        : "r"(a[0]), "r"(a[1]), "r"(a[2]), "r"(a[3]), "r"(b[0]), "r"(b[1]));
}
#define LDSM4(R, addr) \
    asm volatile("ldmatrix.sync.aligned.m8n8.x4.shared.b16 {%0,%1,%2,%3}, [%4];" \
        : "=r"((R)[0]), "=r"((R)[1]), "=r"((R)[2]), "=r"((R)[3]) : "r"(addr))
#define LDSM2(R, addr) \
    asm volatile("ldmatrix.sync.aligned.m8n8.x2.shared.b16 {%0,%1}, [%2];" \
        : "=r"((R)[0]), "=r"((R)[1]) : "r"(addr))

// ---------------- kernel 0: convert x to fp16 + zero state ----------------
__global__ void conv_x_kernel(const float* __restrict__ x) {
    int gi = blockIdx.x * 256 + threadIdx.x;
    int i = gi * 4;
    float4 v = *(const float4*)(x + i);
    __half2 p0 = __floats2half2_rn(v.x, v.y);
    __half2 p1 = __floats2half2_rn(v.z, v.w);
    uint2 o; o.x = h2u(p0); o.y = h2u(p1);
    *(uint2*)(g_xch + i) = o;
    if (gi < MAXP) ((int*)g_tok_pair)[gi] = -1;
    if (gi >= MAXP && gi < MAXP + NR) g_counts[gi - MAXP] = 0;
}

// ---------------- kernel 1: router (fp32), 8 tokens per block -------------
__global__ void __launch_bounds__(128) router_kernel(
    const float* __restrict__ x, const float* __restrict__ rw,
    const float* __restrict__ bias)
{
    int t0 = blockIdx.x * 8;
    __shared__ float s_logit[8][ETOT];
    int tid = threadIdx.x;
    int warp = tid >> 5, lane = tid & 31;
    const float* xr = x + (size_t)t0 * HID;
    for (int e = warp; e < ETOT; e += 4) {
        const float* wr = rw + (size_t)e * HID;
        float a[8];
        #pragma unroll
        for (int u = 0; u < 8; u++) a[u] = 0.f;
        #pragma unroll 2
        for (int j = lane; j < HID; j += 32) {
            float wv = wr[j];
            #pragma unroll
            for (int u = 0; u < 8; u++) a[u] += xr[j + u * HID] * wv;
        }
        #pragma unroll
        for (int o = 16; o; o >>= 1)
            #pragma unroll
            for (int u = 0; u < 8; u++) a[u] += __shfl_xor_sync(0xffffffffu, a[u], o);
        if (lane == 0) {
            #pragma unroll
            for (int u = 0; u < 8; u++) s_logit[u][e] = a[u];
        }
    }
    __syncthreads();
    if (tid < 8) {
        int t = t0 + tid;
        float score[ETOT], sel[ETOT];
        for (int e = 0; e < ETOT; e++) {
            float s = 1.f / (1.f + expf(-s_logit[tid][e]));
            score[e] = s;
            sel[e] = s + bias[e];
        }
        float zsum = 0.f;
        for (int k = 0; k < TOPK; k++) {
            int best = -1; float bv = -1e30f;
            for (int e = 0; e < ETOT; e++)
                if (sel[e] > bv) { bv = sel[e]; best = e; }
            sel[best] = -1e30f;
            if (best < NR) {
                g_topk_id[t][k] = best;
                g_topk_w[t][k]  = score[best];
                atomicAdd(&g_counts[best], 1);
            } else {
                g_topk_id[t][k] = -1;
                g_topk_w[t][k]  = 0.f;
                zsum += score[best];
            }
        }
        g_zero_sum[t] = zsum;
    }
}

// ---------------- kernel 2: compaction (with fused offsets scan) ----------
__global__ void __launch_bounds__(1024) scatter_kernel() {
    int e = blockIdx.x;
    int t = threadIdx.x;
    __shared__ int s_cnt[NR];
    if (t < NR) s_cnt[t] = g_counts[t];

    float w = 0.f; int flag = 0; int kmatch = 0;
    #pragma unroll
    for (int k = 0; k < TOPK; k++)
        if (g_topk_id[t][k] == e) { flag = 1; w = g_topk_w[t][k]; kmatch = k; }

    __shared__ int warp_sums[32];
    int lane = t & 31, wid = t >> 5;
    int v = flag;
    #pragma unroll
    for (int o = 1; o < 32; o <<= 1) {
        int n = __shfl_up_sync(0xffffffffu, v, o);
        if (lane >= o) v += n;
    }
    if (lane == 31) warp_sums[wid] = v;
    __syncthreads();
    if (wid == 0) {
        int s = warp_sums[lane];
        #pragma unroll
        for (int o = 1; o < 32; o <<= 1) {
            int n = __shfl_up_sync(0xffffffffu, s, o);
            if (lane >= o) s += n;
        }
        warp_sums[lane] = s;
    }
    __syncthreads();
    int off = 0;
    for (int i = 0; i < e; i++) off += s_cnt[i];
    if (t == 0) {
        g_offsets[e] = off;
        if (e == NR - 1) g_offsets[NR] = off + s_cnt[e];
    }
    int incl = v + (wid > 0 ? warp_sums[wid - 1] : 0);
    if (flag) {
        int idx = off + incl - 1;
        g_pair_tok[idx] = t;
        g_pair_w[idx]   = w;
        g_tok_pair[t][kmatch] = idx;
    }
}

// ============ SMEM layout: natural row-major half tiles, 64B rows ==========
// swizzle: 16B-column index ^= (row>>1)&3

// ---------------- kernel 3: stage 1 (x@w1g, x@w1u, SwiGLU) -----------------
// CTA tile: 128 gathered tokens x 64 inter cols; warps 4(m) x 2(n).
__global__ void __launch_bounds__(256, 2) stage1_kernel(
    const float* __restrict__ w1g, const float* __restrict__ w1u)
{
    int e   = blockIdx.y;
    int off = g_offsets[e];
    int cnt = g_offsets[e + 1] - off;
    int m0  = blockIdx.z * 128;
    if (m0 >= cnt) return;
    int i0 = blockIdx.x * 64;

    extern __shared__ __align__(16) char smem[];
    int* s_tok = (int*)smem;
    char* Abuf = smem + 1024;            // 2 x 8192 (128 rows x 64B)
    char* Gbuf = smem + 1024 + 16384;    // 2 x 4096 (64 rows x 64B)
    char* Ubuf = smem + 1024 + 24576;    // 2 x 4096
    uint32_t sbase = smem_u32(smem);
    uint32_t aA = sbase + 1024, aG = aA + 16384, aU = aG + 8192;

    int tid = threadIdx.x, lane = tid & 31, wid = tid >> 5;
    int wm = wid >> 1, wn = wid & 1;
    if (tid < 128) {
        int m = m0 + tid;
        s_tok[tid] = (m < cnt) ? g_pair_tok[off + m] : -1;
    }
    __syncthreads();

    int lrow = lane & 7;
    int asel = lane >> 3;
    int arow = ((asel & 1) << 3) | lrow;
    int ahi  = asel >> 1;
    int aswz = (arow >> 1) & 3;
    int bhi  = (lane >> 3) & 1;
    int bswz = (lrow >> 1) & 3;

    const float* gbase = w1g + ((size_t)e * INTER + i0) * HID;
    const float* ubase = w1u + ((size_t)e * INTER + i0) * HID;

    float accG[2][4][4], accU[2][4][4];
    #pragma unroll
    for (int a = 0; a < 2; a++)
        #pragma unroll
        for (int b = 0; b < 4; b++)
            #pragma unroll
            for (int c = 0; c < 4; c++) { accG[a][b][c] = 0.f; accU[a][b][c] = 0.f; }

    uint4 rxa[2]; float4 rg[2], ru[2];
    auto ldg_chunk = [&](int it) {
        int k0 = it * 32;
        #pragma unroll
        for (int i = 0; i < 2; i++) {
            int idx = tid + i * 256; int r = idx >> 2, q = idx & 3;
            int tok = s_tok[r];
            rxa[i] = (tok >= 0) ? *(const uint4*)(g_xch + (size_t)tok * HID + k0 + q * 8)
                                : make_uint4(0u, 0u, 0u, 0u);
        }
        #pragma unroll
        for (int i = 0; i < 2; i++) {
            int idx = tid + i * 256; int r = idx >> 3, q = idx & 7;
            size_t go = (size_t)r * HID + k0 + q * 4;
            rg[i] = *(const float4*)(gbase + go);
            ru[i] = *(const float4*)(ubase + go);
        }
    };
    auto sts_chunk = [&](int buf) {
        char* A = Abuf + buf * 8192;
        char* G = Gbuf + buf * 4096;
        char* U = Ubuf + buf * 4096;
        #pragma unroll
        for (int i = 0; i < 2; i++) {
            int idx = tid + i * 256; int r = idx >> 2, q = idx & 3;
            *(uint4*)(A + r * 64 + ((q ^ ((r >> 1) & 3)) << 4)) = rxa[i];
        }
        #pragma unroll
        for (int i = 0; i < 2; i++) {
            int idx = tid + i * 256; int r = idx >> 3, q = idx & 7;
            int so = r * 64 + ((((q >> 1) ^ ((r >> 1) & 3)) << 4) | ((q & 1) << 3));
            uint2 vg; vg.x = h2u(__floats2half2_rn(rg[i].x, rg[i].y));
                      vg.y = h2u(__floats2half2_rn(rg[i].z, rg[i].w));
            *(uint2*)(G + so) = vg;
            uint2 vu; vu.x = h2u(__floats2half2_rn(ru[i].x, ru[i].y));
                      vu.y = h2u(__floats2half2_rn(ru[i].z, ru[i].w));
            *(uint2*)(U + so) = vu;
        }
    };
    auto compute = [&](int buf) {
        uint32_t bA = aA + buf * 8192;
        uint32_t bG = aG + buf * 4096;
        uint32_t bU = aU + buf * 4096;
        #pragma unroll
        for (int s = 0; s < 2; s++) {
            uint32_t af[2][4];
            int ac = (((2 * s + ahi) ^ aswz) << 4) + arow * 64;
            LDSM4(af[0], bA + (wm * 2)     * 1024 + ac);
            LDSM4(af[1], bA + (wm * 2 + 1) * 1024 + ac);
            int bc = (((2 * s + bhi) ^ bswz) << 4) + lrow * 64;
            #pragma unroll
            for (int t = 0; t < 4; t++) {
                int nt = wn * 4 + t;
                uint32_t bg[2], bu[2];
                LDSM2(bg, bG + nt * 512 + bc);
                LDSM2(bu, bU + nt * 512 + bc);
                mma_f16(accG[0][t], af[0], bg);
                mma_f16(accG[1][t], af[1], bg);
                mma_f16(accU[0][t], af[0], bu);
                mma_f16(accU[1][t], af[1], bu);
            }
        }
    };

    ldg_chunk(0); sts_chunk(0);
    __syncthreads();
    for (int it = 0; it < CH1; ++it) {
        bool pf = (it + 1) < CH1;
        if (pf) ldg_chunk(it + 1);
        compute(it & 1);
        if (pf) sts_chunk((it + 1) & 1);
        __syncthreads();
    }

    // epilogue: h = silu(g)*u -> fp16 g_h
    #pragma unroll
    for (int mi = 0; mi < 2; mi++) {
        int rbase = wm * 32 + mi * 16 + (lane >> 2);
        #pragma unroll
        for (int t = 0; t < 4; t++) {
            int col = i0 + wn * 32 + t * 8 + (lane & 3) * 2;
            #pragma unroll
            for (int half = 0; half < 2; half++) {
                int rloc = rbase + half * 8;
                int m = m0 + rloc;
                if (m < cnt) {
                    float g0 = accG[mi][t][half * 2],     u0 = accU[mi][t][half * 2];
                    float g1 = accG[mi][t][half * 2 + 1], u1 = accU[mi][t][half * 2 + 1];
                    float h0 = (g0 / (1.f + __expf(-g0))) * u0;
                    float h1 = (g1 / (1.f + __expf(-g1))) * u1;
                    *(__half2*)(g_h + (size_t)(off + m) * INTER + col) =
                        __floats2half2_rn(h0, h1);
                }
            }
        }
    }
}

// ---------------- kernel 4: stage 2 (h @ w2, weighted) ---------------------
// CTA tile: 128 pairs x 128 hidden cols; warps 4(m) x 2(n).
__global__ void __launch_bounds__(256, 2) stage2_kernel(const float* __restrict__ w2)
{
    int e   = blockIdx.y;
    int off = g_offsets[e];
    int cnt = g_offsets[e + 1] - off;
    int m0  = blockIdx.z * 128;
    if (m0 >= cnt) return;
    int n0 = blockIdx.x * 128;

    extern __shared__ __align__(16) char smem[];
    float* s_w = (float*)smem;
    char* Abuf = smem + 1024;            // 2 x 8192
    char* Bbuf = smem + 1024 + 16384;    // 2 x 8192 (128 n-rows x 64B)
    uint32_t sbase = smem_u32(smem);
    uint32_t aA = sbase + 1024, aB = aA + 16384;

    int tid = threadIdx.x, lane = tid & 31, wid = tid >> 5;
    int wm = wid >> 1, wn = wid & 1;
    if (tid < 128) {
        int m = m0 + tid;
        s_w[tid] = (m < cnt) ? g_pair_w[off + m] : 0.f;
    }
    __syncthreads();

    int lrow = lane & 7;
    int asel = lane >> 3;
    int arow = ((asel & 1) << 3) | lrow;
    int ahi  = asel >> 1;
    int aswz = (arow >> 1) & 3;
    int bhi  = (lane >> 3) & 1;
    int bswz = (lrow >> 1) & 3;

    const float* bbase = w2 + ((size_t)e * HID + n0) * INTER;

    float acc[2][8][4];
    #pragma unroll
    for (int a = 0; a < 2; a++)
        #pragma unroll
        for (int b = 0; b < 8; b++)
            #pragma unroll
            for (int c = 0; c < 4; c++) acc[a][b][c] = 0.f;

    uint4 rxa[2]; float4 rb0[2], rb1[2];
    auto ldg_chunk = [&](int it) {
        int k0 = it * 32;
        #pragma unroll
        for (int i = 0; i < 2; i++) {
            int idx = tid + i * 256; int r = idx >> 2, q = idx & 3;
            int m = m0 + r;
            rxa[i] = (m < cnt) ? *(const uint4*)(g_h + (size_t)(off + m) * INTER + k0 + q * 8)
                               : make_uint4(0u, 0u, 0u, 0u);
            size_t o = (size_t)r * INTER + k0 + q * 8;
            rb0[i] = *(const float4*)(bbase + o);
            rb1[i] = *(const float4*)(bbase + o + 4);
        }
    };
    auto sts_chunk = [&](int buf) {
        #pragma unroll
        for (int i = 0; i < 2; i++) {
            int idx = tid + i * 256; int r = idx >> 2, q = idx & 3;
            int so = r * 64 + ((q ^ ((r >> 1) & 3)) << 4);
            *(uint4*)(Abuf + buf * 8192 + so) = rxa[i];
            uint4 vb;
            vb.x = h2u(__floats2half2_rn(rb0[i].x, rb0[i].y));
            vb.y = h2u(__floats2half2_rn(rb0[i].z, rb0[i].w));
            vb.z = h2u(__floats2half2_rn(rb1[i].x, rb1[i].y));
            vb.w = h2u(__floats2half2_rn(rb1[i].z, rb1[i].w));
            *(uint4*)(Bbuf + buf * 8192 + so) = vb;
        }
    };
    auto compute = [&](int buf) {
        uint32_t bA = aA + buf * 8192;
        uint32_t bB = aB + buf * 8192;
        #pragma unroll
        for (int s = 0; s < 2; s++) {
            uint32_t af[2][4];
            int ac = (((2 * s + ahi) ^ aswz) << 4) + arow * 64;
            LDSM4(af[0], bA + (wm * 2)     * 1024 + ac);
            LDSM4(af[1], bA + (wm * 2 + 1) * 1024 + ac);
            int bc = (((2 * s + bhi) ^ bswz) << 4) + lrow * 64;
            #pragma unroll
            for (int t = 0; t < 8; t++) {
                int nt = wn * 8 + t;
                uint32_t bf[2];
                LDSM2(bf, bB + nt * 512 + bc);
                mma_f16(acc[0][t], af[0], bf);
                mma_f16(acc[1][t], af[1], bf);
            }
        }
    };

    ldg_chunk(0); sts_chunk(0);
    __syncthreads();
    for (int it = 0; it < CH2; ++it) {
        bool pf = (it + 1) < CH2;
        if (pf) ldg_chunk(it + 1);
        compute(it & 1);
        if (pf) sts_chunk((it + 1) & 1);
        __syncthreads();
    }

    // epilogue: weighted rows into g_ye (fp16)
    #pragma unroll
    for (int mi = 0; mi < 2; mi++) {
        int rbase = wm * 32 + mi * 16 + (lane >> 2);
        #pragma unroll
        for (int t = 0; t < 8; t++) {
            int col = n0 + wn * 64 + t * 8 + (lane & 3) * 2;
            #pragma unroll
            for (int half = 0; half < 2; half++) {
                int rloc = rbase + half * 8;
                int m = m0 + rloc;
                if (m < cnt) {
                    float pw = s_w[rloc];
                    *(__half2*)(g_ye + (size_t)(off + m) * HID + col) =
                        __floats2half2_rn(pw * acc[mi][t][half * 2],
                                          pw * acc[mi][t][half * 2 + 1]);
                }
            }
        }
    }
}

// ---------------- kernel 5: combine ---------------------------------------
__global__ void __launch_bounds__(256) combine_kernel(
    const float* __restrict__ x, float* __restrict__ out)
{
    int t = blockIdx.x;
    int c = threadIdx.x * 8;
    float zs = g_zero_sum[t];
    const float* xr = x + (size_t)t * HID + c;
    float4 a0 = *(const float4*)xr;
    float4 a1 = *(const float4*)(xr + 4);
    a0.x *= zs; a0.y *= zs; a0.z *= zs; a0.w *= zs;
    a1.x *= zs; a1.y *= zs; a1.z *= zs; a1.w *= zs;
    #pragma unroll
    for (int k = 0; k < TOPK; k++) {
        int p = g_tok_pair[t][k];
        if (p >= 0) {
            uint4 raw = *(const uint4*)(g_ye + (size_t)p * HID + c);
            __half2* hp = (__half2*)&raw;
            float2 f0 = __half22float2(hp[0]);
            float2 f1 = __half22float2(hp[1]);
            float2 f2 = __half22float2(hp[2]);
            float2 f3 = __half22float2(hp[3]);
            a0.x += f0.x; a0.y += f0.y; a0.z += f1.x; a0.w += f1.y;
            a1.x += f2.x; a1.y += f2.y; a1.z += f3.x; a1.w += f3.y;
        }
    }
    a0.x *= RSF; a0.y *= RSF; a0.z *= RSF; a0.w *= RSF;
    a1.x *= RSF; a1.y *= RSF; a1.z *= RSF; a1.w *= RSF;
    float* o = out + (size_t)t * HID + c;
    *(float4*)o = a0;
    *(float4*)(o + 4) = a1;
}

// ---------------- launch ---------------------------------------------------
extern "C" void kernel_launch(void* const* d_in, const int* in_sizes, int n_in,
                              void* d_out, int out_size)
{
    const float* x    = (const float*)d_in[0];
    const float* rw   = (const float*)d_in[1];
    const float* bias = (const float*)d_in[2];
    const float* w1g  = (const float*)d_in[3];
    const float* w1u  = (const float*)d_in[4];
    const float* w2   = (const float*)d_in[5];
    float* out = (float*)d_out;

    cudaFuncSetAttribute(stage1_kernel, cudaFuncAttributeMaxDynamicSharedMemorySize, SMEM_SZ);
    cudaFuncSetAttribute(stage2_kernel, cudaFuncAttributeMaxDynamicSharedMemorySize, SMEM_SZ);

    conv_x_kernel<<<(T_TOKENS * HID) / (256 * 4), 256>>>(x);
    router_kernel<<<T_TOKENS / 8, 128>>>(x, rw, bias);
    scatter_kernel<<<NR, 1024>>>();
    // grid.z = 2: max 256 tokens/expert (binomial bound, mean ~105, max ~140;
    // validated on this seed in the R10 run)
    stage1_kernel<<<dim3(INTER / 64, NR, 2), 256, SMEM_SZ>>>(w1g, w1u);
    stage2_kernel<<<dim3(HID / 128, NR, 2), 256, SMEM_SZ>>>(w2);
    combine_kernel<<<T_TOKENS, 256>>>(x, out);
}

// round 15
// speedup vs baseline: 1.5571x; 1.0018x over previous
#include <cuda_runtime.h>
#include <cuda_fp16.h>
#include <cstdint>
#include <math.h>

// Problem constants
#define T_TOKENS 1024
#define HID      2048
#define INTER    1024
#define NR       32
#define ETOT     40
#define TOPK     4
#define MAXP     (T_TOKENS * TOPK)
#define RSF      1.0f

#define CH1      (HID / 32)     // 64 K-chunks (chunk K = 32) in stage 1
#define CH2      (INTER / 32)   // 32 K-chunks in stage 2
#define SMEM_SZ  33792

// ---------------- device scratch ------------------------------------------
__device__ int   g_topk_id[T_TOKENS][TOPK];
__device__ float g_topk_w [T_TOKENS][TOPK];
__device__ float g_zero_sum[T_TOKENS];
__device__ int   g_counts [NR];
__device__ int   g_offsets[NR + 1];
__device__ int   g_pair_tok[MAXP];
__device__ float g_pair_w [MAXP];
__device__ __align__(16) __half g_xch[(size_t)T_TOKENS * HID];  // rn(x) fp16, 4MB
__device__ __align__(16) __half g_h  [(size_t)MAXP * INTER];    // rn(h) fp16, 8MB

// ---------------- helpers --------------------------------------------------
__device__ __forceinline__ uint32_t smem_u32(const void* p) {
    uint32_t a;
    asm("{ .reg .u64 t; cvta.to.shared.u64 t, %1; cvt.u32.u64 %0, t; }"
        : "=r"(a) : "l"(p));
    return a;
}
__device__ __forceinline__ uint32_t h2u(__half2 h) {
    return *reinterpret_cast<uint32_t*>(&h);
}

__device__ __forceinline__ void mma_f16(float* d, const uint32_t* a, const uint32_t* b) {
    asm volatile(
        "mma.sync.aligned.m16n8k16.row.col.f32.f16.f16.f32 "
        "{%0,%1,%2,%3}, {%4,%5,%6,%7}, {%8,%9}, {%0,%1,%2,%3};"
        : "+f"(d[0]), "+f"(d[1]), "+f"(d[2]), "+f"(d[3])
        : "r"(a[0]), "r"(a[1]), "r"(a[2]), "r"(a[3]), "r"(b[0]), "r"(b[1]));
}
#define LDSM4(R, addr) \
    asm volatile("ldmatrix.sync.aligned.m8n8.x4.shared.b16 {%0,%1,%2,%3}, [%4];" \
        : "=r"((R)[0]), "=r"((R)[1]), "=r"((R)[2]), "=r"((R)[3]) : "r"(addr))
#define LDSM2(R, addr) \
    asm volatile("ldmatrix.sync.aligned.m8n8.x2.shared.b16 {%0,%1}, [%2];" \
        : "=r"((R)[0]), "=r"((R)[1]) : "r"(addr))

// ---------------- kernel 0: convert x to fp16 + zero counts ---------------
__global__ void conv_x_kernel(const float* __restrict__ x) {
    int gi = blockIdx.x * 256 + threadIdx.x;
    int i = gi * 4;
    float4 v = *(const float4*)(x + i);
    __half2 p0 = __floats2half2_rn(v.x, v.y);
    __half2 p1 = __floats2half2_rn(v.z, v.w);
    uint2 o; o.x = h2u(p0); o.y = h2u(p1);
    *(uint2*)(g_xch + i) = o;
    if (gi < NR) g_counts[gi] = 0;
}

// ---------------- kernel 1: router (fp32), 8 tokens per block -------------
__global__ void __launch_bounds__(128) router_kernel(
    const float* __restrict__ x, const float* __restrict__ rw,
    const float* __restrict__ bias)
{
    int t0 = blockIdx.x * 8;
    __shared__ float s_logit[8][ETOT];
    int tid = threadIdx.x;
    int warp = tid >> 5, lane = tid & 31;
    const float* xr = x + (size_t)t0 * HID;
    for (int e = warp; e < ETOT; e += 4) {
        const float* wr = rw + (size_t)e * HID;
        float a[8];
        #pragma unroll
        for (int u = 0; u < 8; u++) a[u] = 0.f;
        #pragma unroll 2
        for (int j = lane; j < HID; j += 32) {
            float wv = wr[j];
            #pragma unroll
            for (int u = 0; u < 8; u++) a[u] += xr[j + u * HID] * wv;
        }
        #pragma unroll
        for (int o = 16; o; o >>= 1)
            #pragma unroll
            for (int u = 0; u < 8; u++) a[u] += __shfl_xor_sync(0xffffffffu, a[u], o);
        if (lane == 0) {
            #pragma unroll
            for (int u = 0; u < 8; u++) s_logit[u][e] = a[u];
        }
    }
    __syncthreads();
    if (tid < 8) {
        int t = t0 + tid;
        float score[ETOT], sel[ETOT];
        for (int e = 0; e < ETOT; e++) {
            float s = 1.f / (1.f + expf(-s_logit[tid][e]));
            score[e] = s;
            sel[e] = s + bias[e];
        }
        float zsum = 0.f;
        for (int k = 0; k < TOPK; k++) {
            int best = -1; float bv = -1e30f;
            for (int e = 0; e < ETOT; e++)
                if (sel[e] > bv) { bv = sel[e]; best = e; }
            sel[best] = -1e30f;
            if (best < NR) {
                g_topk_id[t][k] = best;
                g_topk_w[t][k]  = score[best];
                atomicAdd(&g_counts[best], 1);
            } else {
                g_topk_id[t][k] = -1;
                g_topk_w[t][k]  = 0.f;
                zsum += score[best];
            }
        }
        g_zero_sum[t] = zsum;
    }
}

// ---------------- kernel 2: compaction (with fused offsets scan) ----------
__global__ void __launch_bounds__(1024) scatter_kernel() {
    int e = blockIdx.x;
    int t = threadIdx.x;
    __shared__ int s_cnt[NR];
    if (t < NR) s_cnt[t] = g_counts[t];

    float w = 0.f; int flag = 0;
    #pragma unroll
    for (int k = 0; k < TOPK; k++)
        if (g_topk_id[t][k] == e) { flag = 1; w = g_topk_w[t][k]; }

    __shared__ int warp_sums[32];
    int lane = t & 31, wid = t >> 5;
    int v = flag;
    #pragma unroll
    for (int o = 1; o < 32; o <<= 1) {
        int n = __shfl_up_sync(0xffffffffu, v, o);
        if (lane >= o) v += n;
    }
    if (lane == 31) warp_sums[wid] = v;
    __syncthreads();
    if (wid == 0) {
        int s = warp_sums[lane];
        #pragma unroll
        for (int o = 1; o < 32; o <<= 1) {
            int n = __shfl_up_sync(0xffffffffu, s, o);
            if (lane >= o) s += n;
        }
        warp_sums[lane] = s;
    }
    __syncthreads();
    int off = 0;
    for (int i = 0; i < e; i++) off += s_cnt[i];
    if (t == 0) {
        g_offsets[e] = off;
        if (e == NR - 1) g_offsets[NR] = off + s_cnt[e];
    }
    int incl = v + (wid > 0 ? warp_sums[wid - 1] : 0);
    if (flag) {
        int idx = off + incl - 1;
        g_pair_tok[idx] = t;
        g_pair_w[idx]   = w;
    }
}

// ---------------- kernel 3: init out with zero-expert term ----------------
__global__ void __launch_bounds__(256) init_out_kernel(
    const float* __restrict__ x, float* __restrict__ out)
{
    int gi = blockIdx.x * 256 + threadIdx.x;
    int i = gi * 4;
    int t = i >> 11;   // / HID
    float zs = g_zero_sum[t] * RSF;
    float4 v = *(const float4*)(x + i);
    v.x *= zs; v.y *= zs; v.z *= zs; v.w *= zs;
    *(float4*)(out + i) = v;
}

// ============ SMEM layout: natural row-major half tiles, 64B rows ==========
// swizzle: 16B-column index ^= (row>>1)&3

// ---------------- kernel 4: stage 1 (x@w1g, x@w1u, SwiGLU) -----------------
// CTA tile: 128 gathered tokens x 64 inter cols; warps 4(m) x 2(n).
__global__ void __launch_bounds__(256, 2) stage1_kernel(
    const float* __restrict__ w1g, const float* __restrict__ w1u)
{
    int e   = blockIdx.y;
    int off = g_offsets[e];
    int cnt = g_offsets[e + 1] - off;
    int m0  = blockIdx.z * 128;
    if (m0 >= cnt) return;
    int i0 = blockIdx.x * 64;

    extern __shared__ __align__(16) char smem[];
    int* s_tok = (int*)smem;
    char* Abuf = smem + 1024;            // 2 x 8192 (128 rows x 64B)
    char* Gbuf = smem + 1024 + 16384;    // 2 x 4096 (64 rows x 64B)
    char* Ubuf = smem + 1024 + 24576;    // 2 x 4096
    uint32_t sbase = smem_u32(smem);
    uint32_t aA = sbase + 1024, aG = aA + 16384, aU = aG + 8192;

    int tid = threadIdx.x, lane = tid & 31, wid = tid >> 5;
    int wm = wid >> 1, wn = wid & 1;
    if (tid < 128) {
        int m = m0 + tid;
        s_tok[tid] = (m < cnt) ? g_pair_tok[off + m] : -1;
    }
    __syncthreads();

    int lrow = lane & 7;
    int asel = lane >> 3;
    int arow = ((asel & 1) << 3) | lrow;
    int ahi  = asel >> 1;
    int aswz = (arow >> 1) & 3;
    int bhi  = (lane >> 3) & 1;
    int bswz = (lrow >> 1) & 3;

    const float* gbase = w1g + ((size_t)e * INTER + i0) * HID;
    const float* ubase = w1u + ((size_t)e * INTER + i0) * HID;

    float accG[2][4][4], accU[2][4][4];
    #pragma unroll
    for (int a = 0; a < 2; a++)
        #pragma unroll
        for (int b = 0; b < 4; b++)
            #pragma unroll
            for (int c = 0; c < 4; c++) { accG[a][b][c] = 0.f; accU[a][b][c] = 0.f; }

    uint4 rxa[2]; float4 rg[2], ru[2];
    auto ldg_chunk = [&](int it) {
        int k0 = it * 32;
        #pragma unroll
        for (int i = 0; i < 2; i++) {
            int idx = tid + i * 256; int r = idx >> 2, q = idx & 3;
            int tok = s_tok[r];
            rxa[i] = (tok >= 0) ? *(const uint4*)(g_xch + (size_t)tok * HID + k0 + q * 8)
                                : make_uint4(0u, 0u, 0u, 0u);
        }
        #pragma unroll
        for (int i = 0; i < 2; i++) {
            int idx = tid + i * 256; int r = idx >> 3, q = idx & 7;
            size_t go = (size_t)r * HID + k0 + q * 4;
            rg[i] = *(const float4*)(gbase + go);
            ru[i] = *(const float4*)(ubase + go);
        }
    };
    auto sts_chunk = [&](int buf) {
        char* A = Abuf + buf * 8192;
        char* G = Gbuf + buf * 4096;
        char* U = Ubuf + buf * 4096;
        #pragma unroll
        for (int i = 0; i < 2; i++) {
            int idx = tid + i * 256; int r = idx >> 2, q = idx & 3;
            *(uint4*)(A + r * 64 + ((q ^ ((r >> 1) & 3)) << 4)) = rxa[i];
        }
        #pragma unroll
        for (int i = 0; i < 2; i++) {
            int idx = tid + i * 256; int r = idx >> 3, q = idx & 7;
            int so = r * 64 + ((((q >> 1) ^ ((r >> 1) & 3)) << 4) | ((q & 1) << 3));
            uint2 vg; vg.x = h2u(__floats2half2_rn(rg[i].x, rg[i].y));
                      vg.y = h2u(__floats2half2_rn(rg[i].z, rg[i].w));
            *(uint2*)(G + so) = vg;
            uint2 vu; vu.x = h2u(__floats2half2_rn(ru[i].x, ru[i].y));
                      vu.y = h2u(__floats2half2_rn(ru[i].z, ru[i].w));
            *(uint2*)(U + so) = vu;
        }
    };
    auto compute = [&](int buf) {
        uint32_t bA = aA + buf * 8192;
        uint32_t bG = aG + buf * 4096;
        uint32_t bU = aU + buf * 4096;
        #pragma unroll
        for (int s = 0; s < 2; s++) {
            uint32_t af[2][4];
            int ac = (((2 * s + ahi) ^ aswz) << 4) + arow * 64;
            LDSM4(af[0], bA + (wm * 2)     * 1024 + ac);
            LDSM4(af[1], bA + (wm * 2 + 1) * 1024 + ac);
            int bc = (((2 * s + bhi) ^ bswz) << 4) + lrow * 64;
            #pragma unroll
            for (int t = 0; t < 4; t++) {
                int nt = wn * 4 + t;
                uint32_t bg[2], bu[2];
                LDSM2(bg, bG + nt * 512 + bc);
                LDSM2(bu, bU + nt * 512 + bc);
                mma_f16(accG[0][t], af[0], bg);
                mma_f16(accG[1][t], af[1], bg);
                mma_f16(accU[0][t], af[0], bu);
                mma_f16(accU[1][t], af[1], bu);
            }
        }
    };

    ldg_chunk(0); sts_chunk(0);
    __syncthreads();
    for (int it = 0; it < CH1; ++it) {
        bool pf = (it + 1) < CH1;
        if (pf) ldg_chunk(it + 1);
        compute(it & 1);
        if (pf) sts_chunk((it + 1) & 1);
        __syncthreads();
    }

    // epilogue: h = silu(g)*u -> fp16 g_h
    #pragma unroll
    for (int mi = 0; mi < 2; mi++) {
        int rbase = wm * 32 + mi * 16 + (lane >> 2);
        #pragma unroll
        for (int t = 0; t < 4; t++) {
            int col = i0 + wn * 32 + t * 8 + (lane & 3) * 2;
            #pragma unroll
            for (int half = 0; half < 2; half++) {
                int rloc = rbase + half * 8;
                int m = m0 + rloc;
                if (m < cnt) {
                    float g0 = accG[mi][t][half * 2],     u0 = accU[mi][t][half * 2];
                    float g1 = accG[mi][t][half * 2 + 1], u1 = accU[mi][t][half * 2 + 1];
                    float h0 = (g0 / (1.f + __expf(-g0))) * u0;
                    float h1 = (g1 / (1.f + __expf(-g1))) * u1;
                    *(__half2*)(g_h + (size_t)(off + m) * INTER + col) =
                        __floats2half2_rn(h0, h1);
                }
            }
        }
    }
}

// ---------------- kernel 5: stage 2 (h @ w2, weighted, atomic combine) -----
// CTA tile: 128 pairs x 128 hidden cols; warps 4(m) x 2(n).
// Epilogue: out[tok] += pw * acc  (fp32 REDG; <=4 addends per element).
__global__ void __launch_bounds__(256, 2) stage2_kernel(
    const float* __restrict__ w2, float* __restrict__ out)
{
    int e   = blockIdx.y;
    int off = g_offsets[e];
    int cnt = g_offsets[e + 1] - off;
    int m0  = blockIdx.z * 128;
    if (m0 >= cnt) return;
    int n0 = blockIdx.x * 128;

    extern __shared__ __align__(16) char smem[];
    float* s_w  = (float*)smem;
    int*   s_tk = (int*)(smem + 512);
    char* Abuf = smem + 1024;            // 2 x 8192
    char* Bbuf = smem + 1024 + 16384;    // 2 x 8192 (128 n-rows x 64B)
    uint32_t sbase = smem_u32(smem);
    uint32_t aA = sbase + 1024, aB = aA + 16384;

    int tid = threadIdx.x, lane = tid & 31, wid = tid >> 5;
    int wm = wid >> 1, wn = wid & 1;
    if (tid < 128) {
        int m = m0 + tid;
        if (m < cnt) { s_w[tid] = g_pair_w[off + m]; s_tk[tid] = g_pair_tok[off + m]; }
        else         { s_w[tid] = 0.f;               s_tk[tid] = 0; }
    }
    __syncthreads();

    int lrow = lane & 7;
    int asel = lane >> 3;
    int arow = ((asel & 1) << 3) | lrow;
    int ahi  = asel >> 1;
    int aswz = (arow >> 1) & 3;
    int bhi  = (lane >> 3) & 1;
    int bswz = (lrow >> 1) & 3;

    const float* bbase = w2 + ((size_t)e * HID + n0) * INTER;

    float acc[2][8][4];
    #pragma unroll
    for (int a = 0; a < 2; a++)
        #pragma unroll
        for (int b = 0; b < 8; b++)
            #pragma unroll
            for (int c = 0; c < 4; c++) acc[a][b][c] = 0.f;

    uint4 rxa[2]; float4 rb0[2], rb1[2];
    auto ldg_chunk = [&](int it) {
        int k0 = it * 32;
        #pragma unroll
        for (int i = 0; i < 2; i++) {
            int idx = tid + i * 256; int r = idx >> 2, q = idx & 3;
            int m = m0 + r;
            rxa[i] = (m < cnt) ? *(const uint4*)(g_h + (size_t)(off + m) * INTER + k0 + q * 8)
                               : make_uint4(0u, 0u, 0u, 0u);
            size_t o = (size_t)r * INTER + k0 + q * 8;
            rb0[i] = *(const float4*)(bbase + o);
            rb1[i] = *(const float4*)(bbase + o + 4);
        }
    };
    auto sts_chunk = [&](int buf) {
        #pragma unroll
        for (int i = 0; i < 2; i++) {
            int idx = tid + i * 256; int r = idx >> 2, q = idx & 3;
            int so = r * 64 + ((q ^ ((r >> 1) & 3)) << 4);
            *(uint4*)(Abuf + buf * 8192 + so) = rxa[i];
            uint4 vb;
            vb.x = h2u(__floats2half2_rn(rb0[i].x, rb0[i].y));
            vb.y = h2u(__floats2half2_rn(rb0[i].z, rb0[i].w));
            vb.z = h2u(__floats2half2_rn(rb1[i].x, rb1[i].y));
            vb.w = h2u(__floats2half2_rn(rb1[i].z, rb1[i].w));
            *(uint4*)(Bbuf + buf * 8192 + so) = vb;
        }
    };
    auto compute = [&](int buf) {
        uint32_t bA = aA + buf * 8192;
        uint32_t bB = aB + buf * 8192;
        #pragma unroll
        for (int s = 0; s < 2; s++) {
            uint32_t af[2][4];
            int ac = (((2 * s + ahi) ^ aswz) << 4) + arow * 64;
            LDSM4(af[0], bA + (wm * 2)     * 1024 + ac);
            LDSM4(af[1], bA + (wm * 2 + 1) * 1024 + ac);
            int bc = (((2 * s + bhi) ^ bswz) << 4) + lrow * 64;
            #pragma unroll
            for (int t = 0; t < 8; t++) {
                int nt = wn * 8 + t;
                uint32_t bf[2];
                LDSM2(bf, bB + nt * 512 + bc);
                mma_f16(acc[0][t], af[0], bf);
                mma_f16(acc[1][t], af[1], bf);
            }
        }
    };

    ldg_chunk(0); sts_chunk(0);
    __syncthreads();
    for (int it = 0; it < CH2; ++it) {
        bool pf = (it + 1) < CH2;
        if (pf) ldg_chunk(it + 1);
        compute(it & 1);
        if (pf) sts_chunk((it + 1) & 1);
        __syncthreads();
    }

    // epilogue: out[tok] += pw * acc (REDG fp32)
    #pragma unroll
    for (int mi = 0; mi < 2; mi++) {
        int rbase = wm * 32 + mi * 16 + (lane >> 2);
        #pragma unroll
        for (int t = 0; t < 8; t++) {
            int col = n0 + wn * 64 + t * 8 + (lane & 3) * 2;
            #pragma unroll
            for (int half = 0; half < 2; half++) {
                int rloc = rbase + half * 8;
                int m = m0 + rloc;
                if (m < cnt) {
                    float pw = s_w[rloc] * RSF;
                    float* orow = out + (size_t)s_tk[rloc] * HID + col;
                    atomicAdd(orow,     pw * acc[mi][t][half * 2]);
                    atomicAdd(orow + 1, pw * acc[mi][t][half * 2 + 1]);
                }
            }
        }
    }
}

// ---------------- launch ---------------------------------------------------
extern "C" void kernel_launch(void* const* d_in, const int* in_sizes, int n_in,
                              void* d_out, int out_size)
{
    const float* x    = (const float*)d_in[0];
    const float* rw   = (const float*)d_in[1];
    const float* bias = (const float*)d_in[2];
    const float* w1g  = (const float*)d_in[3];
    const float* w1u  = (const float*)d_in[4];
    const float* w2   = (const float*)d_in[5];
    float* out = (float*)d_out;

    cudaFuncSetAttribute(stage1_kernel, cudaFuncAttributeMaxDynamicSharedMemorySize, SMEM_SZ);
    cudaFuncSetAttribute(stage2_kernel, cudaFuncAttributeMaxDynamicSharedMemorySize, SMEM_SZ);

    conv_x_kernel<<<(T_TOKENS * HID) / (256 * 4), 256>>>(x);
    router_kernel<<<T_TOKENS / 8, 128>>>(x, rw, bias);
    scatter_kernel<<<NR, 1024>>>();
    init_out_kernel<<<(T_TOKENS * HID) / (256 * 4), 256>>>(x, out);
    // grid.z = 2: max 256 tokens/expert (binomial bound, mean ~105)
    stage1_kernel<<<dim3(INTER / 64, NR, 2), 256, SMEM_SZ>>>(w1g, w1u);
    stage2_kernel<<<dim3(HID / 128, NR, 2), 256, SMEM_SZ>>>(w2, out);
}

// round 17
// speedup vs baseline: 1.8767x; 1.2052x over previous
#include <cuda_runtime.h>
#include <cuda_fp16.h>
#include <cstdint>
#include <math.h>

// Problem constants
#define T_TOKENS 1024
#define HID      2048
#define INTER    1024
#define NR       32
#define ETOT     40
#define TOPK     4
#define MAXP     (T_TOKENS * TOPK)
#define RSF      1.0f

#define CH1      (HID / 32)     // 64 K-chunks (chunk K = 32) in stage 1
#define CH2      (INTER / 32)   // 32 K-chunks in stage 2
#define SMEM_SZ  33792

// ---------------- device scratch ------------------------------------------
__device__ int   g_topk_id[T_TOKENS][TOPK];
__device__ float g_topk_w [T_TOKENS][TOPK];
__device__ float g_zero_sum[T_TOKENS];
__device__ int   g_counts [NR];
__device__ int   g_offsets[NR + 1];
__device__ int   g_pair_tok[MAXP];
__device__ float g_pair_w [MAXP];
__device__ __align__(16) __half g_xch[(size_t)T_TOKENS * HID];  // rn(x) fp16, 4MB
__device__ __align__(16) __half g_h  [(size_t)MAXP * INTER];    // rn(h) fp16, 8MB

// ---------------- helpers --------------------------------------------------
__device__ __forceinline__ uint32_t smem_u32(const void* p) {
    uint32_t a;
    asm("{ .reg .u64 t; cvta.to.shared.u64 t, %1; cvt.u32.u64 %0, t; }"
        : "=r"(a) : "l"(p));
    return a;
}
__device__ __forceinline__ uint32_t h2u(__half2 h) {
    return *reinterpret_cast<uint32_t*>(&h);
}

__device__ __forceinline__ void mma_f16(float* d, const uint32_t* a, const uint32_t* b) {
    asm volatile(
        "mma.sync.aligned.m16n8k16.row.col.f32.f16.f16.f32 "
        "{%0,%1,%2,%3}, {%4,%5,%6,%7}, {%8,%9}, {%0,%1,%2,%3};"
        : "+f"(d[0]), "+f"(d[1]), "+f"(d[2]), "+f"(d[3])
        : "r"(a[0]), "r"(a[1]), "r"(a[2]), "r"(a[3]), "r"(b[0]), "r"(b[1]));
}
#define LDSM4(R, addr) \
    asm volatile("ldmatrix.sync.aligned.m8n8.x4.shared.b16 {%0,%1,%2,%3}, [%4];" \
        : "=r"((R)[0]), "=r"((R)[1]), "=r"((R)[2]), "=r"((R)[3]) : "r"(addr))
#define LDSM2(R, addr) \
    asm volatile("ldmatrix.sync.aligned.m8n8.x2.shared.b16 {%0,%1}, [%2];" \
        : "=r"((R)[0]), "=r"((R)[1]) : "r"(addr))

// ---------------- kernel 0: convert x to fp16 + zero counts ---------------
__global__ void conv_x_kernel(const float* __restrict__ x) {
    int gi = blockIdx.x * 256 + threadIdx.x;
    int i = gi * 4;
    float4 v = *(const float4*)(x + i);
    __half2 p0 = __floats2half2_rn(v.x, v.y);
    __half2 p1 = __floats2half2_rn(v.z, v.w);
    uint2 o; o.x = h2u(p0); o.y = h2u(p1);
    *(uint2*)(g_xch + i) = o;
    if (gi < NR) g_counts[gi] = 0;
}

// ---------------- kernel 1: router (fp32), 4 tokens per block -------------
__global__ void __launch_bounds__(128) router_kernel(
    const float* __restrict__ x, const float* __restrict__ rw,
    const float* __restrict__ bias)
{
    int t0 = blockIdx.x * 4;
    __shared__ float s_logit[4][ETOT];
    int tid = threadIdx.x;
    int warp = tid >> 5, lane = tid & 31;
    const float* xr = x + (size_t)t0 * HID;
    for (int e = warp; e < ETOT; e += 4) {
        const float* wr = rw + (size_t)e * HID;
        float a0 = 0.f, a1 = 0.f, a2 = 0.f, a3 = 0.f;
        #pragma unroll 4
        for (int j = lane; j < HID; j += 32) {
            float wv = wr[j];
            a0 += xr[j] * wv;
            a1 += xr[j + HID] * wv;
            a2 += xr[j + 2 * HID] * wv;
            a3 += xr[j + 3 * HID] * wv;
        }
        #pragma unroll
        for (int o = 16; o; o >>= 1) {
            a0 += __shfl_xor_sync(0xffffffffu, a0, o);
            a1 += __shfl_xor_sync(0xffffffffu, a1, o);
            a2 += __shfl_xor_sync(0xffffffffu, a2, o);
            a3 += __shfl_xor_sync(0xffffffffu, a3, o);
        }
        if (lane == 0) {
            s_logit[0][e] = a0; s_logit[1][e] = a1;
            s_logit[2][e] = a2; s_logit[3][e] = a3;
        }
    }
    __syncthreads();
    if (tid < 4) {
        int t = t0 + tid;
        float score[ETOT], sel[ETOT];
        for (int e = 0; e < ETOT; e++) {
            float s = 1.f / (1.f + expf(-s_logit[tid][e]));
            score[e] = s;
            sel[e] = s + bias[e];
        }
        float zsum = 0.f;
        for (int k = 0; k < TOPK; k++) {
            int best = -1; float bv = -1e30f;
            for (int e = 0; e < ETOT; e++)
                if (sel[e] > bv) { bv = sel[e]; best = e; }
            sel[best] = -1e30f;
            if (best < NR) {
                g_topk_id[t][k] = best;
                g_topk_w[t][k]  = score[best];
                atomicAdd(&g_counts[best], 1);
            } else {
                g_topk_id[t][k] = -1;
                g_topk_w[t][k]  = 0.f;
                zsum += score[best];
            }
        }
        g_zero_sum[t] = zsum;
    }
}

// ---------------- kernel 2: compaction (with fused offsets scan) ----------
__global__ void __launch_bounds__(1024) scatter_kernel() {
    int e = blockIdx.x;
    int t = threadIdx.x;
    __shared__ int s_cnt[NR];
    if (t < NR) s_cnt[t] = g_counts[t];

    float w = 0.f; int flag = 0;
    #pragma unroll
    for (int k = 0; k < TOPK; k++)
        if (g_topk_id[t][k] == e) { flag = 1; w = g_topk_w[t][k]; }

    __shared__ int warp_sums[32];
    int lane = t & 31, wid = t >> 5;
    int v = flag;
    #pragma unroll
    for (int o = 1; o < 32; o <<= 1) {
        int n = __shfl_up_sync(0xffffffffu, v, o);
        if (lane >= o) v += n;
    }
    if (lane == 31) warp_sums[wid] = v;
    __syncthreads();
    if (wid == 0) {
        int s = warp_sums[lane];
        #pragma unroll
        for (int o = 1; o < 32; o <<= 1) {
            int n = __shfl_up_sync(0xffffffffu, s, o);
            if (lane >= o) s += n;
        }
        warp_sums[lane] = s;
    }
    __syncthreads();
    int off = 0;
    for (int i = 0; i < e; i++) off += s_cnt[i];
    if (t == 0) {
        g_offsets[e] = off;
        if (e == NR - 1) g_offsets[NR] = off + s_cnt[e];
    }
    int incl = v + (wid > 0 ? warp_sums[wid - 1] : 0);
    if (flag) {
        int idx = off + incl - 1;
        g_pair_tok[idx] = t;
        g_pair_w[idx]   = w;
    }
}

// ---------------- kernel 3: init out with zero-expert term ----------------
__global__ void __launch_bounds__(256) init_out_kernel(
    const float* __restrict__ x, float* __restrict__ out)
{
    int gi = blockIdx.x * 256 + threadIdx.x;
    int i = gi * 4;
    int t = i >> 11;   // / HID
    float zs = g_zero_sum[t] * RSF;
    float4 v = *(const float4*)(x + i);
    v.x *= zs; v.y *= zs; v.z *= zs; v.w *= zs;
    *(float4*)(out + i) = v;
}

// ============ SMEM layout: natural row-major half tiles, 64B rows ==========
// swizzle: 16B-column index ^= (row>>1)&3

// ---------------- kernel 4: stage 1 (x@w1g, x@w1u, SwiGLU) -----------------
// CTA tile: 128 gathered tokens x 64 inter cols; warps 4(m) x 2(n).
__global__ void __launch_bounds__(256, 2) stage1_kernel(
    const float* __restrict__ w1g, const float* __restrict__ w1u)
{
    int e   = blockIdx.y;
    int off = g_offsets[e];
    int cnt = g_offsets[e + 1] - off;
    int m0  = blockIdx.z * 128;
    if (m0 >= cnt) return;
    int i0 = blockIdx.x * 64;

    extern __shared__ __align__(16) char smem[];
    int* s_tok = (int*)smem;
    char* Abuf = smem + 1024;            // 2 x 8192 (128 rows x 64B)
    char* Gbuf = smem + 1024 + 16384;    // 2 x 4096 (64 rows x 64B)
    char* Ubuf = smem + 1024 + 24576;    // 2 x 4096
    uint32_t sbase = smem_u32(smem);
    uint32_t aA = sbase + 1024, aG = aA + 16384, aU = aG + 8192;

    int tid = threadIdx.x, lane = tid & 31, wid = tid >> 5;
    int wm = wid >> 1, wn = wid & 1;
    if (tid < 128) {
        int m = m0 + tid;
        s_tok[tid] = (m < cnt) ? g_pair_tok[off + m] : -1;
    }
    __syncthreads();

    int lrow = lane & 7;
    int asel = lane >> 3;
    int arow = ((asel & 1) << 3) | lrow;
    int ahi  = asel >> 1;
    int aswz = (arow >> 1) & 3;
    int bhi  = (lane >> 3) & 1;
    int bswz = (lrow >> 1) & 3;

    const float* gbase = w1g + ((size_t)e * INTER + i0) * HID;
    const float* ubase = w1u + ((size_t)e * INTER + i0) * HID;

    float accG[2][4][4], accU[2][4][4];
    #pragma unroll
    for (int a = 0; a < 2; a++)
        #pragma unroll
        for (int b = 0; b < 4; b++)
            #pragma unroll
            for (int c = 0; c < 4; c++) { accG[a][b][c] = 0.f; accU[a][b][c] = 0.f; }

    uint4 rxa[2]; float4 rg[2], ru[2];
    auto ldg_chunk = [&](int it) {
        int k0 = it * 32;
        #pragma unroll
        for (int i = 0; i < 2; i++) {
            int idx = tid + i * 256; int r = idx >> 2, q = idx & 3;
            int tok = s_tok[r];
            rxa[i] = (tok >= 0) ? *(const uint4*)(g_xch + (size_t)tok * HID + k0 + q * 8)
                                : make_uint4(0u, 0u, 0u, 0u);
        }
        #pragma unroll
        for (int i = 0; i < 2; i++) {
            int idx = tid + i * 256; int r = idx >> 3, q = idx & 7;
            size_t go = (size_t)r * HID + k0 + q * 4;
            rg[i] = *(const float4*)(gbase + go);
            ru[i] = *(const float4*)(ubase + go);
        }
    };
    auto sts_chunk = [&](int buf) {
        char* A = Abuf + buf * 8192;
        char* G = Gbuf + buf * 4096;
        char* U = Ubuf + buf * 4096;
        #pragma unroll
        for (int i = 0; i < 2; i++) {
            int idx = tid + i * 256; int r = idx >> 2, q = idx & 3;
            *(uint4*)(A + r * 64 + ((q ^ ((r >> 1) & 3)) << 4)) = rxa[i];
        }
        #pragma unroll
        for (int i = 0; i < 2; i++) {
            int idx = tid + i * 256; int r = idx >> 3, q = idx & 7;
            int so = r * 64 + ((((q >> 1) ^ ((r >> 1) & 3)) << 4) | ((q & 1) << 3));
            uint2 vg; vg.x = h2u(__floats2half2_rn(rg[i].x, rg[i].y));
                      vg.y = h2u(__floats2half2_rn(rg[i].z, rg[i].w));
            *(uint2*)(G + so) = vg;
            uint2 vu; vu.x = h2u(__floats2half2_rn(ru[i].x, ru[i].y));
                      vu.y = h2u(__floats2half2_rn(ru[i].z, ru[i].w));
            *(uint2*)(U + so) = vu;
        }
    };
    auto compute = [&](int buf) {
        uint32_t bA = aA + buf * 8192;
        uint32_t bG = aG + buf * 4096;
        uint32_t bU = aU + buf * 4096;
        #pragma unroll
        for (int s = 0; s < 2; s++) {
            uint32_t af[2][4];
            int ac = (((2 * s + ahi) ^ aswz) << 4) + arow * 64;
            LDSM4(af[0], bA + (wm * 2)     * 1024 + ac);
            LDSM4(af[1], bA + (wm * 2 + 1) * 1024 + ac);
            int bc = (((2 * s + bhi) ^ bswz) << 4) + lrow * 64;
            #pragma unroll
            for (int t = 0; t < 4; t++) {
                int nt = wn * 4 + t;
                uint32_t bg[2], bu[2];
                LDSM2(bg, bG + nt * 512 + bc);
                LDSM2(bu, bU + nt * 512 + bc);
                mma_f16(accG[0][t], af[0], bg);
                mma_f16(accG[1][t], af[1], bg);
                mma_f16(accU[0][t], af[0], bu);
                mma_f16(accU[1][t], af[1], bu);
            }
        }
    };

    ldg_chunk(0); sts_chunk(0);
    __syncthreads();
    for (int it = 0; it < CH1; ++it) {
        bool pf = (it + 1) < CH1;
        if (pf) ldg_chunk(it + 1);
        compute(it & 1);
        if (pf) sts_chunk((it + 1) & 1);
        __syncthreads();
    }

    // epilogue: h = silu(g)*u -> fp16 g_h
    #pragma unroll
    for (int mi = 0; mi < 2; mi++) {
        int rbase = wm * 32 + mi * 16 + (lane >> 2);
        #pragma unroll
        for (int t = 0; t < 4; t++) {
            int col = i0 + wn * 32 + t * 8 + (lane & 3) * 2;
            #pragma unroll
            for (int half = 0; half < 2; half++) {
                int rloc = rbase + half * 8;
                int m = m0 + rloc;
                if (m < cnt) {
                    float g0 = accG[mi][t][half * 2],     u0 = accU[mi][t][half * 2];
                    float g1 = accG[mi][t][half * 2 + 1], u1 = accU[mi][t][half * 2 + 1];
                    float h0 = (g0 / (1.f + __expf(-g0))) * u0;
                    float h1 = (g1 / (1.f + __expf(-g1))) * u1;
                    *(__half2*)(g_h + (size_t)(off + m) * INTER + col) =
                        __floats2half2_rn(h0, h1);
                }
            }
        }
    }
}

// ---------------- kernel 5: stage 2 (h @ w2, weighted, atomic combine) -----
// CTA tile: 128 pairs x 128 hidden cols; warps 4(m) x 2(n).
// Epilogue: out[tok] += pw * acc  (fp32 REDG; <=4 addends per element).
__global__ void __launch_bounds__(256, 2) stage2_kernel(
    const float* __restrict__ w2, float* __restrict__ out)
{
    int e   = blockIdx.y;
    int off = g_offsets[e];
    int cnt = g_offsets[e + 1] - off;
    int m0  = blockIdx.z * 128;
    if (m0 >= cnt) return;
    int n0 = blockIdx.x * 128;

    extern __shared__ __align__(16) char smem[];
    float* s_w  = (float*)smem;
    int*   s_tk = (int*)(smem + 512);
    char* Abuf = smem + 1024;            // 2 x 8192
    char* Bbuf = smem + 1024 + 16384;    // 2 x 8192 (128 n-rows x 64B)
    uint32_t sbase = smem_u32(smem);
    uint32_t aA = sbase + 1024, aB = aA + 16384;

    int tid = threadIdx.x, lane = tid & 31, wid = tid >> 5;
    int wm = wid >> 1, wn = wid & 1;
    if (tid < 128) {
        int m = m0 + tid;
        if (m < cnt) { s_w[tid] = g_pair_w[off + m]; s_tk[tid] = g_pair_tok[off + m]; }
        else         { s_w[tid] = 0.f;               s_tk[tid] = 0; }
    }
    __syncthreads();

    int lrow = lane & 7;
    int asel = lane >> 3;
    int arow = ((asel & 1) << 3) | lrow;
    int ahi  = asel >> 1;
    int aswz = (arow >> 1) & 3;
    int bhi  = (lane >> 3) & 1;
    int bswz = (lrow >> 1) & 3;

    const float* bbase = w2 + ((size_t)e * HID + n0) * INTER;

    float acc[2][8][4];
    #pragma unroll
    for (int a = 0; a < 2; a++)
        #pragma unroll
        for (int b = 0; b < 8; b++)
            #pragma unroll
            for (int c = 0; c < 4; c++) acc[a][b][c] = 0.f;

    uint4 rxa[2]; float4 rb[4];
    auto ldg_chunk = [&](int it) {
        int k0 = it * 32;
        #pragma unroll
        for (int i = 0; i < 2; i++) {
            int idx = tid + i * 256; int r = idx >> 2, q = idx & 3;
            int m = m0 + r;
            rxa[i] = (m < cnt) ? *(const uint4*)(g_h + (size_t)(off + m) * INTER + k0 + q * 8)
                               : make_uint4(0u, 0u, 0u, 0u);
        }
        #pragma unroll
        for (int i = 0; i < 4; i++) {
            int idx = tid + i * 256; int r = idx >> 3, q = idx & 7;
            rb[i] = *(const float4*)(bbase + (size_t)r * INTER + k0 + q * 4);
        }
    };
    auto sts_chunk = [&](int buf) {
        char* A = Abuf + buf * 8192;
        char* B = Bbuf + buf * 8192;
        #pragma unroll
        for (int i = 0; i < 2; i++) {
            int idx = tid + i * 256; int r = idx >> 2, q = idx & 3;
            *(uint4*)(A + r * 64 + ((q ^ ((r >> 1) & 3)) << 4)) = rxa[i];
        }
        #pragma unroll
        for (int i = 0; i < 4; i++) {
            int idx = tid + i * 256; int r = idx >> 3, q = idx & 7;
            int so = r * 64 + ((((q >> 1) ^ ((r >> 1) & 3)) << 4) | ((q & 1) << 3));
            uint2 vb; vb.x = h2u(__floats2half2_rn(rb[i].x, rb[i].y));
                      vb.y = h2u(__floats2half2_rn(rb[i].z, rb[i].w));
            *(uint2*)(B + so) = vb;
        }
    };
    auto compute = [&](int buf) {
        uint32_t bA = aA + buf * 8192;
        uint32_t bB = aB + buf * 8192;
        #pragma unroll
        for (int s = 0; s < 2; s++) {
            uint32_t af[2][4];
            int ac = (((2 * s + ahi) ^ aswz) << 4) + arow * 64;
            LDSM4(af[0], bA + (wm * 2)     * 1024 + ac);
            LDSM4(af[1], bA + (wm * 2 + 1) * 1024 + ac);
            int bc = (((2 * s + bhi) ^ bswz) << 4) + lrow * 64;
            #pragma unroll
            for (int t = 0; t < 8; t++) {
                int nt = wn * 8 + t;
                uint32_t bf[2];
                LDSM2(bf, bB + nt * 512 + bc);
                mma_f16(acc[0][t], af[0], bf);
                mma_f16(acc[1][t], af[1], bf);
            }
        }
    };

    ldg_chunk(0); sts_chunk(0);
    __syncthreads();
    for (int it = 0; it < CH2; ++it) {
        bool pf = (it + 1) < CH2;
        if (pf) ldg_chunk(it + 1);
        compute(it & 1);
        if (pf) sts_chunk((it + 1) & 1);
        __syncthreads();
    }

    // epilogue: out[tok] += pw * acc (REDG fp32)
    #pragma unroll
    for (int mi = 0; mi < 2; mi++) {
        int rbase = wm * 32 + mi * 16 + (lane >> 2);
        #pragma unroll
        for (int t = 0; t < 8; t++) {
            int col = n0 + wn * 64 + t * 8 + (lane & 3) * 2;
            #pragma unroll
            for (int half = 0; half < 2; half++) {
                int rloc = rbase + half * 8;
                int m = m0 + rloc;
                if (m < cnt) {
                    float pw = s_w[rloc] * RSF;
                    float* orow = out + (size_t)s_tk[rloc] * HID + col;
                    atomicAdd(orow,     pw * acc[mi][t][half * 2]);
                    atomicAdd(orow + 1, pw * acc[mi][t][half * 2 + 1]);
                }
            }
        }
    }
}

// ---------------- launch ---------------------------------------------------
extern "C" void kernel_launch(void* const* d_in, const int* in_sizes, int n_in,
                              void* d_out, int out_size)
{
    const float* x    = (const float*)d_in[0];
    const float* rw   = (const float*)d_in[1];
    const float* bias = (const float*)d_in[2];
    const float* w1g  = (const float*)d_in[3];
    const float* w1u  = (const float*)d_in[4];
    const float* w2   = (const float*)d_in[5];
    float* out = (float*)d_out;

    cudaFuncSetAttribute(stage1_kernel, cudaFuncAttributeMaxDynamicSharedMemorySize, SMEM_SZ);
    cudaFuncSetAttribute(stage2_kernel, cudaFuncAttributeMaxDynamicSharedMemorySize, SMEM_SZ);

    conv_x_kernel<<<(T_TOKENS * HID) / (256 * 4), 256>>>(x);
    router_kernel<<<T_TOKENS / 4, 128>>>(x, rw, bias);
    scatter_kernel<<<NR, 1024>>>();
    init_out_kernel<<<(T_TOKENS * HID) / (256 * 4), 256>>>(x, out);
    stage1_kernel<<<dim3(INTER / 64, NR, 8), 256, SMEM_SZ>>>(w1g, w1u);
    stage2_kernel<<<dim3(HID / 128, NR, 8), 256, SMEM_SZ>>>(w2, out);
}